// round 15
// baseline (speedup 1.0000x reference)
#include <cuda_runtime.h>
#include <cuda_bf16.h>
#include <math.h>

#define NB 4
#define NLEN 4096
#define LSEQ 3072
#define NLVL 11
#define TWO_PI 6.28318530717958647692f

typedef unsigned long long u64;

// ---------------- f32x2 helpers ----------------
__device__ __forceinline__ u64 pk(float x, float y) {
    u64 r; asm("mov.b64 %0, {%1, %2};" : "=l"(r) : "f"(x), "f"(y)); return r;
}
__device__ __forceinline__ void upk(u64 v, float& x, float& y) {
    asm("mov.b64 {%0, %1}, %2;" : "=f"(x), "=f"(y) : "l"(v));
}
__device__ __forceinline__ u64 f2(u64 a, u64 b, u64 c) {
    u64 d; asm("fma.rn.f32x2 %0, %1, %2, %3;" : "=l"(d) : "l"(a), "l"(b), "l"(c)); return d;
}
__device__ __forceinline__ u64 fadd2(u64 a, u64 b) {
    u64 d; asm("add.rn.f32x2 %0, %1, %2;" : "=l"(d) : "l"(a), "l"(b)); return d;
}

// ---------------- device scratch ----------------
__device__ float g_vT[(size_t)NB * 64 * NLEN * 8];   // [b][c][t][k]
__device__ float g_coarse[NB * 2 * 512];

#define SPEC_SZ (NLVL * NB * 16 * 512)
__device__ float g_DfR[SPEC_SZ];
__device__ float g_DfI[SPEC_SZ];
__device__ float g_SfR[SPEC_SZ];
__device__ float g_SfI[SPEC_SZ];
__device__ float g_UdFR[SPEC_SZ];
__device__ float g_UdFI[SPEC_SZ];
__device__ float g_UsFR[SPEC_SZ];
__device__ float g_UsFI[SPEC_SZ];

__device__ float g_Wt[(size_t)6 * 16 * 512 * 512];
__device__ u64 g_twF[16 * 4096];
__device__ u64 g_twI[16 * 4096];

// bf16 split operands, K concatenated to 1536: A' = [Ah|Ah|Al], W' = [Wh|Wl|Wh]
__device__ __nv_bfloat16 g_Ax[(size_t)16384 * 1536];
__device__ __nv_bfloat16 g_Wx0[512 * 1536];
__device__ __nv_bfloat16 g_Wx1[512 * 1536];

// ---------------- twiddle tables ----------------
__global__ void twiddle_kernel(u64* __restrict__ twF, u64* __restrict__ twI) {
    int j = blockIdx.y;
    int Lc = NLEN >> (j + 1);
    int idx = blockIdx.x * 256 + threadIdx.x;
    if (idx >= Lc * 16) return;
    int t = idx >> 4, m = idx & 15;
    int toff = 16 * (4096 - (4096 >> j));
    float ang = (TWO_PI / (float)Lc) * (float)(m * t);
    float sv, cv;
    sincosf(ang, &sv, &cv);
    twF[toff + idx] = pk(cv, -sv);
    twI[toff + idx] = pk(cv, sv);
}

// ---------------- bf16 split kernels ----------------
__device__ __forceinline__ void split8(const float* vv, uint4& H, uint4& L) {
    __align__(16) __nv_bfloat16 h[8];
    __align__(16) __nv_bfloat16 l[8];
#pragma unroll
    for (int k = 0; k < 8; k++) {
        h[k] = __float2bfloat16(vv[k]);
        l[k] = __float2bfloat16(vv[k] - __bfloat162float(h[k]));
    }
    H = *(uint4*)h;
    L = *(uint4*)l;
}

__global__ void split_x_kernel(const float* __restrict__ x, __nv_bfloat16* __restrict__ Ax)
{
    int idx = blockIdx.x * 256 + threadIdx.x;      // 16384*64
    int row = idx >> 6, c8 = idx & 63;
    int b = row >> 12, t = row & 4095;
    int srcRow = b * LSEQ + (t < LSEQ ? t : t - LSEQ);
    const float4* s = (const float4*)(x + (size_t)srcRow * 512 + c8 * 8);
    float4 v0 = s[0], v1 = s[1];
    float vv[8] = {v0.x, v0.y, v0.z, v0.w, v1.x, v1.y, v1.z, v1.w};
    uint4 H, L; split8(vv, H, L);
    size_t o = (size_t)row * 1536 + c8 * 8;
    *(uint4*)(Ax + o) = H;
    *(uint4*)(Ax + o + 512) = H;
    *(uint4*)(Ax + o + 1024) = L;
}

__global__ void split_w_kernel(const float* __restrict__ W0, const float* __restrict__ W1,
                               __nv_bfloat16* __restrict__ Wx0, __nv_bfloat16* __restrict__ Wx1)
{
    int idx = blockIdx.x * 256 + threadIdx.x;      // 512*64
    const float* W = blockIdx.y ? W1 : W0;
    __nv_bfloat16* Wx = blockIdx.y ? Wx1 : Wx0;
    int row = idx >> 6, c8 = idx & 63;
    const float4* s = (const float4*)(W + (size_t)row * 512 + c8 * 8);
    float4 v0 = s[0], v1 = s[1];
    float vv[8] = {v0.x, v0.y, v0.z, v0.w, v1.x, v1.y, v1.z, v1.w};
    uint4 H, L; split8(vv, H, L);
    size_t o = (size_t)row * 1536 + c8 * 8;
    *(uint4*)(Wx + o) = H;        // Wh
    *(uint4*)(Wx + o + 512) = L;  // Wl
    *(uint4*)(Wx + o + 1024) = H; // Wh
}

// ---------------- warp-MMA bf16 GEMM ----------------
__device__ __forceinline__ void mma_bf16(float* c, const unsigned* a, const unsigned* b) {
    asm volatile("mma.sync.aligned.m16n8k16.row.col.f32.bf16.bf16.f32 "
        "{%0,%1,%2,%3}, {%4,%5,%6,%7}, {%8,%9}, {%0,%1,%2,%3};"
        : "+f"(c[0]), "+f"(c[1]), "+f"(c[2]), "+f"(c[3])
        : "r"(a[0]), "r"(a[1]), "r"(a[2]), "r"(a[3]), "r"(b[0]), "r"(b[1]));
}

#define KCN 48   // 1536 / 32

__global__ void __launch_bounds__(256) mma_gemm(
    const __nv_bfloat16* __restrict__ A,   // [M][1536]
    const __nv_bfloat16* __restrict__ B,   // [512][1536]
    const float* __restrict__ bias, float* __restrict__ C, int mode)
{
    __shared__ __nv_bfloat16 As[2][128][40];
    __shared__ __nv_bfloat16 Bs[2][128][40];
    int tid = threadIdx.x, lane = tid & 31, wid = tid >> 5;
    int wm = (wid & 3) * 32, wn = (wid >> 2) * 64;
    int m0 = blockIdx.y * 128, nb0 = blockIdx.x * 128;
    int g = lane >> 2, q = lane & 3;
    int r0 = tid >> 2, cq = (tid & 3) * 8;

    uint4 pa0, pa1, pb0, pb1;
#define G2R(kc) do { \
        pa0 = *(const uint4*)(A + (size_t)(m0 + r0) * 1536 + (kc) * 32 + cq); \
        pa1 = *(const uint4*)(A + (size_t)(m0 + r0 + 64) * 1536 + (kc) * 32 + cq); \
        pb0 = *(const uint4*)(B + (size_t)(nb0 + r0) * 1536 + (kc) * 32 + cq); \
        pb1 = *(const uint4*)(B + (size_t)(nb0 + r0 + 64) * 1536 + (kc) * 32 + cq); \
    } while (0)
#define R2S(buf) do { \
        *(uint4*)&As[buf][r0][cq] = pa0; \
        *(uint4*)&As[buf][r0 + 64][cq] = pa1; \
        *(uint4*)&Bs[buf][r0][cq] = pb0; \
        *(uint4*)&Bs[buf][r0 + 64][cq] = pb1; \
    } while (0)

    float acc[2][8][4];
#pragma unroll
    for (int mb = 0; mb < 2; mb++)
#pragma unroll
        for (int nk = 0; nk < 8; nk++)
#pragma unroll
            for (int i = 0; i < 4; i++) acc[mb][nk][i] = 0.f;

    G2R(0);
    R2S(0);
    __syncthreads();

    for (int kc = 0; kc < KCN; kc++) {
        int cur = kc & 1;
        if (kc + 1 < KCN) G2R(kc + 1);
#pragma unroll
        for (int ks = 0; ks < 2; ks++) {
            unsigned af[2][4], bfr[8][2];
#pragma unroll
            for (int mb = 0; mb < 2; mb++) {
                const __nv_bfloat16* ap = &As[cur][wm + mb * 16 + g][ks * 16 + q * 2];
                af[mb][0] = *(const unsigned*)ap;
                af[mb][1] = *(const unsigned*)(ap + 320);
                af[mb][2] = *(const unsigned*)(ap + 8);
                af[mb][3] = *(const unsigned*)(ap + 328);
            }
#pragma unroll
            for (int nk = 0; nk < 8; nk++) {
                const __nv_bfloat16* bp = &Bs[cur][wn + nk * 8 + g][ks * 16 + q * 2];
                bfr[nk][0] = *(const unsigned*)bp;
                bfr[nk][1] = *(const unsigned*)(bp + 8);
            }
#pragma unroll
            for (int mb = 0; mb < 2; mb++)
#pragma unroll
                for (int nk = 0; nk < 8; nk++)
                    mma_bf16(acc[mb][nk], af[mb], bfr[nk]);
        }
        if (kc + 1 < KCN) {
            __syncthreads();
            R2S(cur ^ 1);
            __syncthreads();
        }
    }

#pragma unroll
    for (int mb = 0; mb < 2; mb++) {
        int r = m0 + wm + mb * 16 + g;
#pragma unroll
        for (int nk = 0; nk < 8; nk++) {
            int c = nb0 + wn + nk * 8 + q * 2;
            float b0v = bias[c], b1v = bias[c + 1];
            float2 v01 = make_float2(acc[mb][nk][0] + b0v, acc[mb][nk][1] + b1v);
            float2 v23 = make_float2(acc[mb][nk][2] + b0v, acc[mb][nk][3] + b1v);
            if (mode == 0) {
                int b = r >> 12, t = r & 4095;
                float* base = C + ((size_t)(b * 64 + (c >> 3)) * NLEN) * 8 + (c & 7);
                *(float2*)(base + (size_t)t * 8) = v01;
                *(float2*)(base + (size_t)(t + 8) * 8) = v23;
            } else {
                *(float2*)(C + (size_t)r * 512 + c) = v01;
                *(float2*)(C + (size_t)(r + 8) * 512 + c) = v23;
            }
        }
    }
#undef G2R
#undef R2S
}

// ---------------- weight transpose ----------------
__global__ void transpose_w(const float* __restrict__ Ar, const float* __restrict__ Ai,
                            const float* __restrict__ Br, const float* __restrict__ Bi,
                            const float* __restrict__ Cr, const float* __restrict__ Ci,
                            float* __restrict__ Wt)
{
    const float* src;
    switch (blockIdx.y) {
        case 0: src = Ar; break; case 1: src = Ai; break; case 2: src = Br; break;
        case 3: src = Bi; break; case 4: src = Cr; break; default: src = Ci; break;
    }
    float* dst = Wt + (size_t)blockIdx.y * 16 * 262144;
    int io0 = blockIdx.x * 64;
    __shared__ float sm2[64][17];
    int t = threadIdx.x;
    {
        int ioL = t >> 2; int mq = (t & 3) * 4;
        float4 v = *(const float4*)(src + (size_t)(io0 + ioL) * 16 + mq);
        sm2[ioL][mq] = v.x; sm2[ioL][mq + 1] = v.y; sm2[ioL][mq + 2] = v.z; sm2[ioL][mq + 3] = v.w;
    }
    __syncthreads();
    {
        int m = t >> 4; int g = (t & 15) * 4;
        float* d2 = dst + (size_t)m * 262144 + io0 + g;
        d2[0] = sm2[g][m]; d2[1] = sm2[g + 1][m]; d2[2] = sm2[g + 2][m]; d2[3] = sm2[g + 3][m];
    }
}

#define TWS_STRIDE 18

// ---------------- decomposition level ----------------
__device__ __forceinline__ void decomp_level(
    const float* in, float* out, const u64* coef, const u64* __restrict__ twp,
    u64* tws, int Lout, int t_lane, int k, int tid, u64* accD, u64* accS)
{
    int ntiles = (Lout + 31) >> 5;
    int pr = tid >> 3, pc = (tid & 7) * 2;
    ulonglong2 pre = make_ulonglong2(0ull, 0ull);
    if (pr < Lout) pre = __ldg((const ulonglong2*)(twp + (size_t)pr * 16 + pc));

    for (int tile = 0; tile < ntiles; tile++) {
        __syncthreads();
        tws[pr * TWS_STRIDE + pc] = pre.x;
        tws[pr * TWS_STRIDE + pc + 1] = pre.y;
        __syncthreads();
        int tn = ((tile + 1) << 5) + pr;
        if (tile + 1 < ntiles && tn < Lout)
            pre = __ldg((const ulonglong2*)(twp + (size_t)tn * 16 + pc));

        int t = (tile << 5) + t_lane;
        if (t < Lout) {
            const float4* p = (const float4*)(in + 16 * t);
            float4 q0 = p[0], q1 = p[1], q2 = p[2], q3 = p[3];
            float xa[16] = {q0.x, q0.y, q0.z, q0.w, q1.x, q1.y, q1.z, q1.w,
                            q2.x, q2.y, q2.z, q2.w, q3.x, q3.y, q3.z, q3.w};
            u64 c0 = 0ull, c1 = 0ull, c2 = 0ull, c3 = 0ull;
#pragma unroll
            for (int kk = 0; kk < 16; kk += 4) {
                c0 = f2(pk(xa[kk + 0], xa[kk + 0]), coef[(kk + 0) * 8 + k], c0);
                c1 = f2(pk(xa[kk + 1], xa[kk + 1]), coef[(kk + 1) * 8 + k], c1);
                c2 = f2(pk(xa[kk + 2], xa[kk + 2]), coef[(kk + 2) * 8 + k], c2);
                c3 = f2(pk(xa[kk + 3], xa[kk + 3]), coef[(kk + 3) * 8 + k], c3);
            }
            u64 ds = fadd2(fadd2(c0, c1), fadd2(c2, c3));
            float dv, sv; upk(ds, dv, sv);
            out[8 * t + k] = sv;
            u64 dd = pk(dv, dv), ss = pk(sv, sv);
            const ulonglong2* tp2 = (const ulonglong2*)(tws + t_lane * TWS_STRIDE);
#pragma unroll
            for (int mp = 0; mp < 8; mp += 2) {
                ulonglong2 wA = tp2[mp], wB = tp2[mp + 1];
                int m = mp * 2;
                accD[m + 0] = f2(dd, wA.x, accD[m + 0]);
                accD[m + 1] = f2(dd, wA.y, accD[m + 1]);
                accD[m + 2] = f2(dd, wB.x, accD[m + 2]);
                accD[m + 3] = f2(dd, wB.y, accD[m + 3]);
                accS[m + 0] = f2(ss, wA.x, accS[m + 0]);
                accS[m + 1] = f2(ss, wA.y, accS[m + 1]);
                accS[m + 2] = f2(ss, wB.x, accS[m + 2]);
                accS[m + 3] = f2(ss, wB.y, accS[m + 3]);
            }
        }
    }
}

__device__ __forceinline__ void decomp_reduce(
    u64* accD, u64* accS, u64* red, int tid, int j, int b, int cg,
    float* __restrict__ DfR, float* __restrict__ DfI,
    float* __restrict__ SfR, float* __restrict__ SfI)
{
#pragma unroll
    for (int m = 0; m < 16; m++) {
        accD[m] = fadd2(__shfl_xor_sync(0xffffffffu, accD[m], 8), accD[m]);
        accD[m] = fadd2(__shfl_xor_sync(0xffffffffu, accD[m], 16), accD[m]);
        accS[m] = fadd2(__shfl_xor_sync(0xffffffffu, accS[m], 8), accS[m]);
        accS[m] = fadd2(__shfl_xor_sync(0xffffffffu, accS[m], 16), accS[m]);
    }
    int lane = tid & 31, warp = tid >> 5;
    __syncthreads();
    if (lane < 8) {
        u64* rp = red + (warp * 8 + lane) * 16;
#pragma unroll
        for (int m = 0; m < 16; m++) rp[m] = accD[m];
    }
    __syncthreads();
    if (tid < 128) {
        int k2 = tid >> 4, m = tid & 15;
        u64 s0 = 0ull, s1 = 0ull;
#pragma unroll
        for (int w = 0; w < 8; w += 2) {
            s0 = fadd2(red[(w * 8 + k2) * 16 + m], s0);
            s1 = fadd2(red[((w + 1) * 8 + k2) * 16 + m], s1);
        }
        float R, I; upk(fadd2(s0, s1), R, I);
        size_t o = (((size_t)j * 4 + b) * 16 + m) * 512 + cg * 8 + k2;
        DfR[o] = R; DfI[o] = I;
    }
    __syncthreads();
    if (lane < 8) {
        u64* rp = red + (warp * 8 + lane) * 16;
#pragma unroll
        for (int m = 0; m < 16; m++) rp[m] = accS[m];
    }
    __syncthreads();
    if (tid < 128) {
        int k2 = tid >> 4, m = tid & 15;
        u64 s0 = 0ull, s1 = 0ull;
#pragma unroll
        for (int w = 0; w < 8; w += 2) {
            s0 = fadd2(red[(w * 8 + k2) * 16 + m], s0);
            s1 = fadd2(red[((w + 1) * 8 + k2) * 16 + m], s1);
        }
        float R, I; upk(fadd2(s0, s1), R, I);
        size_t o = (((size_t)j * 4 + b) * 16 + m) * 512 + cg * 8 + k2;
        SfR[o] = R; SfI[o] = I;
    }
    __syncthreads();
}

__global__ void __launch_bounds__(256, 2) decomp_kernel(
    const float* __restrict__ vT, const u64* __restrict__ twF,
    const float* __restrict__ ec_s, const float* __restrict__ ec_d,
    float* __restrict__ DfR, float* __restrict__ DfI,
    float* __restrict__ SfR, float* __restrict__ SfI,
    float* __restrict__ coarse)
{
    extern __shared__ float sm[];
    float* bufB = sm;
    float* bufC = sm + 16384;
    u64* red = (u64*)(sm + 24576);
    u64* coef = red;
    u64* tws = (u64*)(sm + 26624);

    int tid = threadIdx.x;
    int cg = blockIdx.x, b = blockIdx.y;
    int t_lane = tid >> 3, k = tid & 7;

    if (tid < 128) coef[tid] = pk(ec_d[tid], ec_s[tid]);
    __syncthreads();

    const float* gin = vT + (size_t)(b * 64 + cg) * (NLEN * 8);
    u64 accD[16], accS[16];

    {
#pragma unroll
        for (int m = 0; m < 16; m++) { accD[m] = 0ull; accS[m] = 0ull; }
        decomp_level(gin, bufB, coef, twF, tws, 2048, t_lane, k, tid, accD, accS);
        decomp_reduce(accD, accS, red, tid, 0, b, cg, DfR, DfI, SfR, SfI);
        if (tid < 128) coef[tid] = pk(ec_d[tid], ec_s[tid]);
        __syncthreads();
    }

    float* in = bufB;
    float* out = bufC;
    for (int j = 1; j < NLVL; j++) {
        int Lout = 2048 >> j;
        const u64* twp = twF + 16 * (4096 - (4096 >> j));
#pragma unroll
        for (int m = 0; m < 16; m++) { accD[m] = 0ull; accS[m] = 0ull; }
        decomp_level(in, out, coef, twp, tws, Lout, t_lane, k, tid, accD, accS);
        decomp_reduce(accD, accS, red, tid, j, b, cg, DfR, DfI, SfR, SfI);
        if (tid < 128) coef[tid] = pk(ec_d[tid], ec_s[tid]);
        __syncthreads();
        float* tmp = in; in = out; out = tmp;
    }
    if (tid < 16)
        coarse[(b * 2 + (tid >> 3)) * 512 + cg * 8 + (tid & 7)] = in[8 * (tid >> 3) + (tid & 7)];
}

// ---------------- spectral mode mixing (512 thr; xP vectorized [r][ii][4]) ----------------
__global__ void __launch_bounds__(512) mix_kernel(
    const float* __restrict__ Wt,
    const float* __restrict__ DfR, const float* __restrict__ DfI,
    const float* __restrict__ SfR, const float* __restrict__ SfI,
    float* __restrict__ UdFR, float* __restrict__ UdFI,
    float* __restrict__ UsFR, float* __restrict__ UsFI)
{
    int m = blockIdx.x;
    int o0 = blockIdx.y * 64;
    int tx = threadIdx.x & 63;
    int ty = threadIdx.x >> 6;     // 0..7

    __shared__ float wS[6][16][64];    // 24 KB
    __shared__ u64 xP[48][16][4];      // 24 KB, [r][ii][comp] - comps contiguous (32B/row-ii)

    u64 aUd[6], aUs[6];
#pragma unroll
    for (int r = 0; r < 6; r++) { aUd[r] = 0ull; aUs[r] = 0ull; }

    for (int i0 = 0; i0 < 512; i0 += 16) {
        __syncthreads();
        for (int idx = threadIdx.x; idx < 6 * 16 * 64; idx += 512) {
            int arr = idx >> 10; int rem = idx & 1023; int ii = rem >> 6; int oo = rem & 63;
            wS[arr][ii][oo] = Wt[((size_t)arr * 16 + m) * 262144 + (size_t)(i0 + ii) * 512 + o0 + oo];
        }
        // comp-outer mapping keeps gmem reads coalesced; writes scatter into [r][ii][comp]
        for (int idx = threadIdx.x; idx < 48 * 16 * 4; idx += 512) {
            int comp = idx / 768; int rem = idx - comp * 768; int r = rem >> 4; int ii = rem & 15;
            const float* src = (comp == 0) ? DfR : (comp == 1) ? DfI : (comp == 2) ? SfR : SfI;
            float v = (r < 44) ? src[((size_t)r * 16 + m) * 512 + i0 + ii] : 0.f;
            xP[r][ii][comp] = pk(v, v);
        }
        __syncthreads();
#pragma unroll
        for (int ii = 0; ii < 16; ii++) {
            float ar = wS[0][ii][tx], ai = wS[1][ii][tx];
            float br = wS[2][ii][tx], bi = wS[3][ii][tx];
            float cr = wS[4][ii][tx], ci = wS[5][ii][tx];
            u64 wa  = pk(ar, ai),  wan = pk(-ai, ar);
            u64 wb  = pk(br, bi),  wbn = pk(-bi, br);
            u64 wc  = pk(cr, ci),  wcn = pk(-ci, cr);
#pragma unroll
            for (int rr = 0; rr < 6; rr++) {
                int r = ty + rr * 8;
                const ulonglong2* xp2 = (const ulonglong2*)&xP[r][ii][0];
                ulonglong2 xd = xp2[0];   // (dd, di)
                ulonglong2 xs = xp2[1];   // (ss, si)
                aUd[rr] = f2(xd.x, wa, f2(xd.y, wan, f2(xs.x, wb, f2(xs.y, wbn, aUd[rr]))));
                aUs[rr] = f2(xd.x, wc, f2(xd.y, wcn, aUs[rr]));
            }
        }
    }
#pragma unroll
    for (int rr = 0; rr < 6; rr++) {
        int r = ty + rr * 8;
        if (r < 44) {
            size_t idx = ((size_t)r * 16 + m) * 512 + o0 + tx;
            float x, y;
            upk(aUd[rr], x, y); UdFR[idx] = x; UdFI[idx] = y;
            upk(aUs[rr], x, y); UsFR[idx] = x; UsFI[idx] = y;
        }
    }
}

// ---------------- recon level (aout != null => write bf16 split directly) ----------------
__device__ __forceinline__ void recon_level(
    const float* in, float* out, const u64* rcoef, const u64* __restrict__ twp,
    u64* tws,
    const float* __restrict__ UdFR, const float* __restrict__ UdFI,
    const float* __restrict__ UsFR, const float* __restrict__ UsFI,
    size_t specBase, int l, int nyq, float invL, int tmax,
    int t_lane, int k, int lane, int tid, __nv_bfloat16* aout)
{
    u64 vUd[16], vUs[16];
#pragma unroll
    for (int m = 0; m < 16; m++) {
        if (m < l) {
            size_t o = specBase + (size_t)m * 512;
            bool spec = (m == 0) || (nyq && m == l - 1);
            float sc = (spec ? 1.f : 2.f) * invL;
            vUd[m] = pk(sc * UdFR[o], spec ? 0.f : -sc * UdFI[o]);
            vUs[m] = pk(sc * UsFR[o], spec ? 0.f : -sc * UsFI[o]);
        } else { vUd[m] = 0ull; vUs[m] = 0ull; }
    }
    int base = lane & 24;
    int ntiles = (tmax + 31) >> 5;
    int pr = tid >> 3, pc = (tid & 7) * 2;
    ulonglong2 pre = make_ulonglong2(0ull, 0ull);
    if (pr < tmax) pre = __ldg((const ulonglong2*)(twp + (size_t)pr * 16 + pc));

    for (int tile = 0; tile < ntiles; tile++) {
        __syncthreads();
        tws[pr * TWS_STRIDE + pc] = pre.x;
        tws[pr * TWS_STRIDE + pc + 1] = pre.y;
        __syncthreads();
        int tn = ((tile + 1) << 5) + pr;
        if (tile + 1 < ntiles && tn < tmax)
            pre = __ldg((const ulonglong2*)(twp + (size_t)tn * 16 + pc));

        int t = (tile << 5) + t_lane;
        bool act = (t < tmax);
        int tc = act ? t : 0;
        const ulonglong2* tp2 = (const ulonglong2*)(tws + (act ? t_lane : 0) * TWS_STRIDE);
        u64 u0 = 0ull, u1 = 0ull, u2 = 0ull, u3 = 0ull;
        u64 s0 = 0ull, s1 = 0ull, s2 = 0ull, s3 = 0ull;
#pragma unroll
        for (int mp = 0; mp < 8; mp += 2) {
            ulonglong2 wA = tp2[mp], wB = tp2[mp + 1];
            int m = mp * 2;
            u0 = f2(wA.x, vUd[m + 0], u0);
            u1 = f2(wA.y, vUd[m + 1], u1);
            u2 = f2(wB.x, vUd[m + 2], u2);
            u3 = f2(wB.y, vUd[m + 3], u3);
            s0 = f2(wA.x, vUs[m + 0], s0);
            s1 = f2(wA.y, vUs[m + 1], s1);
            s2 = f2(wB.x, vUs[m + 2], s2);
            s3 = f2(wB.y, vUs[m + 3], s3);
        }
        u64 aU = fadd2(fadd2(u0, u1), fadd2(u2, u3));
        u64 aS = fadd2(fadd2(s0, s1), fadd2(s2, s3));
        float ux, uy, sx, sy; upk(aU, ux, uy); upk(aS, sx, sy);
        float ud = ux + uy;
        float vs = in[8 * tc + k] + (sx + sy);
        float vsg[8], udg[8];
#pragma unroll
        for (int kk = 0; kk < 8; kk++) vsg[kk] = __shfl_sync(0xffffffffu, vs, base | kk);
#pragma unroll
        for (int kk = 0; kk < 8; kk++) udg[kk] = __shfl_sync(0xffffffffu, ud, base | kk);
        u64 c0 = 0ull, c1 = 0ull, c2 = 0ull, c3 = 0ull;
#pragma unroll
        for (int kk = 0; kk < 8; kk += 4) {
            c0 = f2(pk(vsg[kk + 0], vsg[kk + 0]), rcoef[(kk + 0) * 8 + k], c0);
            c1 = f2(pk(vsg[kk + 1], vsg[kk + 1]), rcoef[(kk + 1) * 8 + k], c1);
            c2 = f2(pk(vsg[kk + 2], vsg[kk + 2]), rcoef[(kk + 2) * 8 + k], c2);
            c3 = f2(pk(vsg[kk + 3], vsg[kk + 3]), rcoef[(kk + 3) * 8 + k], c3);
        }
#pragma unroll
        for (int kk = 0; kk < 8; kk += 4) {
            c0 = f2(pk(udg[kk + 0], udg[kk + 0]), rcoef[(8 + kk + 0) * 8 + k], c0);
            c1 = f2(pk(udg[kk + 1], udg[kk + 1]), rcoef[(8 + kk + 1) * 8 + k], c1);
            c2 = f2(pk(udg[kk + 2], udg[kk + 2]), rcoef[(8 + kk + 2) * 8 + k], c2);
            c3 = f2(pk(udg[kk + 3], udg[kk + 3]), rcoef[(8 + kk + 3) * 8 + k], c3);
        }
        u64 acc = fadd2(fadd2(c0, c1), fadd2(c2, c3));
        if (act) {
            float xe, xo; upk(acc, xe, xo);
            if (aout) {
                __nv_bfloat16 h0 = __float2bfloat16(xe);
                __nv_bfloat16 l0 = __float2bfloat16(xe - __bfloat162float(h0));
                __nv_bfloat16 h1 = __float2bfloat16(xo);
                __nv_bfloat16 l1 = __float2bfloat16(xo - __bfloat162float(h1));
                size_t r0 = (size_t)(2 * t) * 1536;
                size_t r1 = r0 + 1536;
                aout[r0] = h0; aout[r0 + 512] = h0; aout[r0 + 1024] = l0;
                aout[r1] = h1; aout[r1 + 512] = h1; aout[r1 + 1024] = l1;
            } else {
                out[16 * t + k] = xe;
                out[16 * t + 8 + k] = xo;
            }
        }
    }
}

__global__ void __launch_bounds__(256, 2) recon_fused(
    const float* __restrict__ coarse, const u64* __restrict__ twI,
    const float* __restrict__ rc_e, const float* __restrict__ rc_o,
    const float* __restrict__ T0_w, const float* __restrict__ T0_b,
    const float* __restrict__ UdFR, const float* __restrict__ UdFI,
    const float* __restrict__ UsFR, const float* __restrict__ UsFI,
    __nv_bfloat16* __restrict__ Ax)
{
    extern __shared__ float sm[];
    float* bufB = sm;
    float* bufC = sm + 16384;
    u64* rcoef = (u64*)(sm + 24576);
    u64* tws = (u64*)(sm + 24832);

    __shared__ float cv[16];

    int tid = threadIdx.x;
    int cg = blockIdx.x, b = blockIdx.y;
    int t_lane = tid >> 3, k = tid & 7, lane = tid & 31;

    if (tid < 128) rcoef[tid] = pk(rc_e[tid], rc_o[tid]);
    if (tid < 16) cv[tid] = coarse[(b * 2 + (tid >> 3)) * 512 + cg * 8 + (tid & 7)];
    __syncthreads();
    if (tid < 16) {
        int tt = tid >> 3, kk = tid & 7;
        float s = T0_b[kk];
#pragma unroll
        for (int kp = 0; kp < 8; kp++) s += T0_w[kk * 8 + kp] * cv[tt * 8 + kp];
        bufB[tid] = s;
    }
    __syncthreads();

    float* in = bufB;
    float* out = bufC;
    for (int i = NLVL - 1; i >= 1; i--) {
        int Lc = 2048 >> i;
        int nf = (Lc >> 1) + 1;
        int l = nf < 16 ? nf : 16;
        int nyq = (l == nf);
        const u64* twp = twI + 16 * (4096 - (4096 >> i));
        size_t specBase = (((size_t)i * 4 + b) * 16) * 512 + cg * 8 + k;
        recon_level(in, out, rcoef, twp, tws, UdFR, UdFI, UsFR, UsFI,
                    specBase, l, nyq, 1.f / (float)Lc, Lc, t_lane, k, lane, tid, (__nv_bfloat16*)0);
        __syncthreads();
        float* tmp = in; in = out; out = tmp;
    }
    // level 0: write bf16 split operand directly (only t < 1536 -> rows < 3072)
    {
        __nv_bfloat16* aout = Ax + (size_t)(b * LSEQ) * 1536 + cg * 8 + k;
        size_t specBase = (((size_t)0 * 4 + b) * 16) * 512 + cg * 8 + k;
        recon_level(in, out, rcoef, twI, tws, UdFR, UdFI, UsFR, UsFI,
                    specBase, 16, 0, 1.f / 2048.f, 1536, t_lane, k, lane, tid, aout);
    }
}

// ---------------- host orchestration ----------------
extern "C" void kernel_launch(void* const* d_in, const int* in_sizes, int n_in,
                              void* d_out, int out_size)
{
    const float* x     = (const float*)d_in[0];
    const float* Lk0_w = (const float*)d_in[1];
    const float* Lk0_b = (const float*)d_in[2];
    const float* Lk1_w = (const float*)d_in[3];
    const float* Lk1_b = (const float*)d_in[4];
    const float* T0_w  = (const float*)d_in[5];
    const float* T0_b  = (const float*)d_in[6];
    const float* Ar    = (const float*)d_in[7];
    const float* Ai    = (const float*)d_in[8];
    const float* Br    = (const float*)d_in[9];
    const float* Bi    = (const float*)d_in[10];
    const float* Cr    = (const float*)d_in[11];
    const float* Ci    = (const float*)d_in[12];
    const float* ec_s  = (const float*)d_in[13];
    const float* ec_d  = (const float*)d_in[14];
    const float* rc_e  = (const float*)d_in[15];
    const float* rc_o  = (const float*)d_in[16];

    float *vT, *coarse, *DfR, *DfI, *SfR, *SfI, *UdFR, *UdFI, *UsFR, *UsFI, *Wt;
    u64 *twF, *twI;
    __nv_bfloat16 *Ax, *Wx0, *Wx1;
    cudaGetSymbolAddress((void**)&vT, g_vT);
    cudaGetSymbolAddress((void**)&coarse, g_coarse);
    cudaGetSymbolAddress((void**)&DfR, g_DfR);
    cudaGetSymbolAddress((void**)&DfI, g_DfI);
    cudaGetSymbolAddress((void**)&SfR, g_SfR);
    cudaGetSymbolAddress((void**)&SfI, g_SfI);
    cudaGetSymbolAddress((void**)&UdFR, g_UdFR);
    cudaGetSymbolAddress((void**)&UdFI, g_UdFI);
    cudaGetSymbolAddress((void**)&UsFR, g_UsFR);
    cudaGetSymbolAddress((void**)&UsFI, g_UsFI);
    cudaGetSymbolAddress((void**)&Wt, g_Wt);
    cudaGetSymbolAddress((void**)&twF, g_twF);
    cudaGetSymbolAddress((void**)&twI, g_twI);
    cudaGetSymbolAddress((void**)&Ax, g_Ax);
    cudaGetSymbolAddress((void**)&Wx0, g_Wx0);
    cudaGetSymbolAddress((void**)&Wx1, g_Wx1);

    const int DECOMP_SMEM = 111104;
    const int RECON_SMEM  = 103936;
    cudaFuncSetAttribute(decomp_kernel, cudaFuncAttributeMaxDynamicSharedMemorySize, DECOMP_SMEM);
    cudaFuncSetAttribute(recon_fused, cudaFuncAttributeMaxDynamicSharedMemorySize, RECON_SMEM);

    twiddle_kernel<<<dim3(128, NLVL), 256>>>(twF, twI);
    transpose_w<<<dim3(4096, 6), 256>>>(Ar, Ai, Br, Bi, Cr, Ci, Wt);
    split_w_kernel<<<dim3(128, 2), 256>>>(Lk0_w, Lk1_w, Wx0, Wx1);
    split_x_kernel<<<4096, 256>>>(x, Ax);

    // Lk0 via warp-MMA tensor cores -> vT
    mma_gemm<<<dim3(4, 128), 256>>>(Ax, Wx0, Lk0_b, vT, 0);

    decomp_kernel<<<dim3(64, NB), 256, DECOMP_SMEM>>>(vT, twF, ec_s, ec_d,
                                                      DfR, DfI, SfR, SfI, coarse);

    // mix: 512 threads/CTA, vectorized xP loads
    mix_kernel<<<dim3(16, 8), 512>>>(Wt, DfR, DfI, SfR, SfI, UdFR, UdFI, UsFR, UsFI);

    // fused recon writes the bf16 split GEMM operand directly into Ax
    recon_fused<<<dim3(64, NB), 256, RECON_SMEM>>>(coarse, twI, rc_e, rc_o, T0_w, T0_b,
                                                   UdFR, UdFI, UsFR, UsFI, Ax);

    // Lk1 via warp-MMA tensor cores -> d_out
    mma_gemm<<<dim3(4, 96), 256>>>(Ax, Wx1, Lk1_b, (float*)d_out, 1);
}

// round 16
// speedup vs baseline: 1.0126x; 1.0126x over previous
#include <cuda_runtime.h>
#include <cuda_bf16.h>
#include <math.h>

#define NB 4
#define NLEN 4096
#define LSEQ 3072
#define NLVL 11
#define TWO_PI 6.28318530717958647692f

typedef unsigned long long u64;

// ---------------- f32x2 helpers ----------------
__device__ __forceinline__ u64 pk(float x, float y) {
    u64 r; asm("mov.b64 %0, {%1, %2};" : "=l"(r) : "f"(x), "f"(y)); return r;
}
__device__ __forceinline__ void upk(u64 v, float& x, float& y) {
    asm("mov.b64 {%0, %1}, %2;" : "=f"(x), "=f"(y) : "l"(v));
}
__device__ __forceinline__ u64 f2(u64 a, u64 b, u64 c) {
    u64 d; asm("fma.rn.f32x2 %0, %1, %2, %3;" : "=l"(d) : "l"(a), "l"(b), "l"(c)); return d;
}
__device__ __forceinline__ u64 fadd2(u64 a, u64 b) {
    u64 d; asm("add.rn.f32x2 %0, %1, %2;" : "=l"(d) : "l"(a), "l"(b)); return d;
}

// ---------------- device scratch ----------------
__device__ float g_vT[(size_t)NB * 64 * NLEN * 8];   // [b][c][t][k]
__device__ float g_coarse[NB * 2 * 512];

#define SPEC_SZ (NLVL * NB * 16 * 512)
__device__ float g_DfR[SPEC_SZ];
__device__ float g_DfI[SPEC_SZ];
__device__ float g_SfR[SPEC_SZ];
__device__ float g_SfI[SPEC_SZ];
__device__ float g_UdFR[SPEC_SZ];
__device__ float g_UdFI[SPEC_SZ];
__device__ float g_UsFR[SPEC_SZ];
__device__ float g_UsFI[SPEC_SZ];

__device__ float g_Wt[(size_t)6 * 16 * 512 * 512];
__device__ u64 g_twF[16 * 4096];
__device__ u64 g_twI[16 * 4096];

// bf16 split operands, K concatenated to 1536: A' = [Ah|Ah|Al], W' = [Wh|Wl|Wh]
__device__ __nv_bfloat16 g_Ax[(size_t)16384 * 1536];
__device__ __nv_bfloat16 g_Wx0[512 * 1536];
__device__ __nv_bfloat16 g_Wx1[512 * 1536];

// ---------------- twiddle tables ----------------
__global__ void twiddle_kernel(u64* __restrict__ twF, u64* __restrict__ twI) {
    int j = blockIdx.y;
    int Lc = NLEN >> (j + 1);
    int idx = blockIdx.x * 256 + threadIdx.x;
    if (idx >= Lc * 16) return;
    int t = idx >> 4, m = idx & 15;
    int toff = 16 * (4096 - (4096 >> j));
    float ang = (TWO_PI / (float)Lc) * (float)(m * t);
    float sv, cv;
    sincosf(ang, &sv, &cv);
    twF[toff + idx] = pk(cv, -sv);
    twI[toff + idx] = pk(cv, sv);
}

// ---------------- bf16 split kernels ----------------
__device__ __forceinline__ void split8(const float* vv, uint4& H, uint4& L) {
    __align__(16) __nv_bfloat16 h[8];
    __align__(16) __nv_bfloat16 l[8];
#pragma unroll
    for (int k = 0; k < 8; k++) {
        h[k] = __float2bfloat16(vv[k]);
        l[k] = __float2bfloat16(vv[k] - __bfloat162float(h[k]));
    }
    H = *(uint4*)h;
    L = *(uint4*)l;
}

__global__ void split_x_kernel(const float* __restrict__ x, __nv_bfloat16* __restrict__ Ax)
{
    int idx = blockIdx.x * 256 + threadIdx.x;      // 16384*64
    int row = idx >> 6, c8 = idx & 63;
    int b = row >> 12, t = row & 4095;
    int srcRow = b * LSEQ + (t < LSEQ ? t : t - LSEQ);
    const float4* s = (const float4*)(x + (size_t)srcRow * 512 + c8 * 8);
    float4 v0 = s[0], v1 = s[1];
    float vv[8] = {v0.x, v0.y, v0.z, v0.w, v1.x, v1.y, v1.z, v1.w};
    uint4 H, L; split8(vv, H, L);
    size_t o = (size_t)row * 1536 + c8 * 8;
    *(uint4*)(Ax + o) = H;
    *(uint4*)(Ax + o + 512) = H;
    *(uint4*)(Ax + o + 1024) = L;
}

__global__ void split_w_kernel(const float* __restrict__ W0, const float* __restrict__ W1,
                               __nv_bfloat16* __restrict__ Wx0, __nv_bfloat16* __restrict__ Wx1)
{
    int idx = blockIdx.x * 256 + threadIdx.x;      // 512*64
    const float* W = blockIdx.y ? W1 : W0;
    __nv_bfloat16* Wx = blockIdx.y ? Wx1 : Wx0;
    int row = idx >> 6, c8 = idx & 63;
    const float4* s = (const float4*)(W + (size_t)row * 512 + c8 * 8);
    float4 v0 = s[0], v1 = s[1];
    float vv[8] = {v0.x, v0.y, v0.z, v0.w, v1.x, v1.y, v1.z, v1.w};
    uint4 H, L; split8(vv, H, L);
    size_t o = (size_t)row * 1536 + c8 * 8;
    *(uint4*)(Wx + o) = H;        // Wh
    *(uint4*)(Wx + o + 512) = L;  // Wl
    *(uint4*)(Wx + o + 1024) = H; // Wh
}

// ---------------- warp-MMA bf16 GEMM ----------------
__device__ __forceinline__ void mma_bf16(float* c, const unsigned* a, const unsigned* b) {
    asm volatile("mma.sync.aligned.m16n8k16.row.col.f32.bf16.bf16.f32 "
        "{%0,%1,%2,%3}, {%4,%5,%6,%7}, {%8,%9}, {%0,%1,%2,%3};"
        : "+f"(c[0]), "+f"(c[1]), "+f"(c[2]), "+f"(c[3])
        : "r"(a[0]), "r"(a[1]), "r"(a[2]), "r"(a[3]), "r"(b[0]), "r"(b[1]));
}

#define KCN 48   // 1536 / 32

__global__ void __launch_bounds__(256) mma_gemm(
    const __nv_bfloat16* __restrict__ A,   // [M][1536]
    const __nv_bfloat16* __restrict__ B,   // [512][1536]
    const float* __restrict__ bias, float* __restrict__ C, int mode)
{
    __shared__ __nv_bfloat16 As[2][128][40];
    __shared__ __nv_bfloat16 Bs[2][128][40];
    int tid = threadIdx.x, lane = tid & 31, wid = tid >> 5;
    int wm = (wid & 3) * 32, wn = (wid >> 2) * 64;
    int m0 = blockIdx.y * 128, nb0 = blockIdx.x * 128;
    int g = lane >> 2, q = lane & 3;
    int r0 = tid >> 2, cq = (tid & 3) * 8;

    uint4 pa0, pa1, pb0, pb1;
#define G2R(kc) do { \
        pa0 = *(const uint4*)(A + (size_t)(m0 + r0) * 1536 + (kc) * 32 + cq); \
        pa1 = *(const uint4*)(A + (size_t)(m0 + r0 + 64) * 1536 + (kc) * 32 + cq); \
        pb0 = *(const uint4*)(B + (size_t)(nb0 + r0) * 1536 + (kc) * 32 + cq); \
        pb1 = *(const uint4*)(B + (size_t)(nb0 + r0 + 64) * 1536 + (kc) * 32 + cq); \
    } while (0)
#define R2S(buf) do { \
        *(uint4*)&As[buf][r0][cq] = pa0; \
        *(uint4*)&As[buf][r0 + 64][cq] = pa1; \
        *(uint4*)&Bs[buf][r0][cq] = pb0; \
        *(uint4*)&Bs[buf][r0 + 64][cq] = pb1; \
    } while (0)

    float acc[2][8][4];
#pragma unroll
    for (int mb = 0; mb < 2; mb++)
#pragma unroll
        for (int nk = 0; nk < 8; nk++)
#pragma unroll
            for (int i = 0; i < 4; i++) acc[mb][nk][i] = 0.f;

    G2R(0);
    R2S(0);
    __syncthreads();

    for (int kc = 0; kc < KCN; kc++) {
        int cur = kc & 1;
        if (kc + 1 < KCN) G2R(kc + 1);
#pragma unroll
        for (int ks = 0; ks < 2; ks++) {
            unsigned af[2][4], bfr[8][2];
#pragma unroll
            for (int mb = 0; mb < 2; mb++) {
                const __nv_bfloat16* ap = &As[cur][wm + mb * 16 + g][ks * 16 + q * 2];
                af[mb][0] = *(const unsigned*)ap;
                af[mb][1] = *(const unsigned*)(ap + 320);
                af[mb][2] = *(const unsigned*)(ap + 8);
                af[mb][3] = *(const unsigned*)(ap + 328);
            }
#pragma unroll
            for (int nk = 0; nk < 8; nk++) {
                const __nv_bfloat16* bp = &Bs[cur][wn + nk * 8 + g][ks * 16 + q * 2];
                bfr[nk][0] = *(const unsigned*)bp;
                bfr[nk][1] = *(const unsigned*)(bp + 8);
            }
#pragma unroll
            for (int mb = 0; mb < 2; mb++)
#pragma unroll
                for (int nk = 0; nk < 8; nk++)
                    mma_bf16(acc[mb][nk], af[mb], bfr[nk]);
        }
        if (kc + 1 < KCN) {
            __syncthreads();
            R2S(cur ^ 1);
            __syncthreads();
        }
    }

#pragma unroll
    for (int mb = 0; mb < 2; mb++) {
        int r = m0 + wm + mb * 16 + g;
#pragma unroll
        for (int nk = 0; nk < 8; nk++) {
            int c = nb0 + wn + nk * 8 + q * 2;
            float b0v = bias[c], b1v = bias[c + 1];
            float2 v01 = make_float2(acc[mb][nk][0] + b0v, acc[mb][nk][1] + b1v);
            float2 v23 = make_float2(acc[mb][nk][2] + b0v, acc[mb][nk][3] + b1v);
            if (mode == 0) {
                int b = r >> 12, t = r & 4095;
                float* base = C + ((size_t)(b * 64 + (c >> 3)) * NLEN) * 8 + (c & 7);
                *(float2*)(base + (size_t)t * 8) = v01;
                *(float2*)(base + (size_t)(t + 8) * 8) = v23;
            } else {
                *(float2*)(C + (size_t)r * 512 + c) = v01;
                *(float2*)(C + (size_t)(r + 8) * 512 + c) = v23;
            }
        }
    }
#undef G2R
#undef R2S
}

// ---------------- weight transpose ----------------
__global__ void transpose_w(const float* __restrict__ Ar, const float* __restrict__ Ai,
                            const float* __restrict__ Br, const float* __restrict__ Bi,
                            const float* __restrict__ Cr, const float* __restrict__ Ci,
                            float* __restrict__ Wt)
{
    const float* src;
    switch (blockIdx.y) {
        case 0: src = Ar; break; case 1: src = Ai; break; case 2: src = Br; break;
        case 3: src = Bi; break; case 4: src = Cr; break; default: src = Ci; break;
    }
    float* dst = Wt + (size_t)blockIdx.y * 16 * 262144;
    int io0 = blockIdx.x * 64;
    __shared__ float sm2[64][17];
    int t = threadIdx.x;
    {
        int ioL = t >> 2; int mq = (t & 3) * 4;
        float4 v = *(const float4*)(src + (size_t)(io0 + ioL) * 16 + mq);
        sm2[ioL][mq] = v.x; sm2[ioL][mq + 1] = v.y; sm2[ioL][mq + 2] = v.z; sm2[ioL][mq + 3] = v.w;
    }
    __syncthreads();
    {
        int m = t >> 4; int g = (t & 15) * 4;
        float* d2 = dst + (size_t)m * 262144 + io0 + g;
        d2[0] = sm2[g][m]; d2[1] = sm2[g + 1][m]; d2[2] = sm2[g + 2][m]; d2[3] = sm2[g + 3][m];
    }
}

#define TWS_STRIDE 18

// ---------------- decomposition level ----------------
__device__ __forceinline__ void decomp_level(
    const float* in, float* out, const u64* coef, const u64* __restrict__ twp,
    u64* tws, int Lout, int t_lane, int k, int tid, u64* accD, u64* accS)
{
    int ntiles = (Lout + 31) >> 5;
    int pr = tid >> 3, pc = (tid & 7) * 2;
    ulonglong2 pre = make_ulonglong2(0ull, 0ull);
    if (pr < Lout) pre = __ldg((const ulonglong2*)(twp + (size_t)pr * 16 + pc));

    for (int tile = 0; tile < ntiles; tile++) {
        __syncthreads();
        tws[pr * TWS_STRIDE + pc] = pre.x;
        tws[pr * TWS_STRIDE + pc + 1] = pre.y;
        __syncthreads();
        int tn = ((tile + 1) << 5) + pr;
        if (tile + 1 < ntiles && tn < Lout)
            pre = __ldg((const ulonglong2*)(twp + (size_t)tn * 16 + pc));

        int t = (tile << 5) + t_lane;
        if (t < Lout) {
            const float4* p = (const float4*)(in + 16 * t);
            float4 q0 = p[0], q1 = p[1], q2 = p[2], q3 = p[3];
            float xa[16] = {q0.x, q0.y, q0.z, q0.w, q1.x, q1.y, q1.z, q1.w,
                            q2.x, q2.y, q2.z, q2.w, q3.x, q3.y, q3.z, q3.w};
            u64 c0 = 0ull, c1 = 0ull, c2 = 0ull, c3 = 0ull;
#pragma unroll
            for (int kk = 0; kk < 16; kk += 4) {
                c0 = f2(pk(xa[kk + 0], xa[kk + 0]), coef[(kk + 0) * 8 + k], c0);
                c1 = f2(pk(xa[kk + 1], xa[kk + 1]), coef[(kk + 1) * 8 + k], c1);
                c2 = f2(pk(xa[kk + 2], xa[kk + 2]), coef[(kk + 2) * 8 + k], c2);
                c3 = f2(pk(xa[kk + 3], xa[kk + 3]), coef[(kk + 3) * 8 + k], c3);
            }
            u64 ds = fadd2(fadd2(c0, c1), fadd2(c2, c3));
            float dv, sv; upk(ds, dv, sv);
            out[8 * t + k] = sv;
            u64 dd = pk(dv, dv), ss = pk(sv, sv);
            const ulonglong2* tp2 = (const ulonglong2*)(tws + t_lane * TWS_STRIDE);
#pragma unroll
            for (int mp = 0; mp < 8; mp += 2) {
                ulonglong2 wA = tp2[mp], wB = tp2[mp + 1];
                int m = mp * 2;
                accD[m + 0] = f2(dd, wA.x, accD[m + 0]);
                accD[m + 1] = f2(dd, wA.y, accD[m + 1]);
                accD[m + 2] = f2(dd, wB.x, accD[m + 2]);
                accD[m + 3] = f2(dd, wB.y, accD[m + 3]);
                accS[m + 0] = f2(ss, wA.x, accS[m + 0]);
                accS[m + 1] = f2(ss, wA.y, accS[m + 1]);
                accS[m + 2] = f2(ss, wB.x, accS[m + 2]);
                accS[m + 3] = f2(ss, wB.y, accS[m + 3]);
            }
        }
    }
}

__device__ __forceinline__ void decomp_reduce(
    u64* accD, u64* accS, u64* red, int tid, int j, int b, int cg,
    float* __restrict__ DfR, float* __restrict__ DfI,
    float* __restrict__ SfR, float* __restrict__ SfI)
{
#pragma unroll
    for (int m = 0; m < 16; m++) {
        accD[m] = fadd2(__shfl_xor_sync(0xffffffffu, accD[m], 8), accD[m]);
        accD[m] = fadd2(__shfl_xor_sync(0xffffffffu, accD[m], 16), accD[m]);
        accS[m] = fadd2(__shfl_xor_sync(0xffffffffu, accS[m], 8), accS[m]);
        accS[m] = fadd2(__shfl_xor_sync(0xffffffffu, accS[m], 16), accS[m]);
    }
    int lane = tid & 31, warp = tid >> 5;
    __syncthreads();
    if (lane < 8) {
        u64* rp = red + (warp * 8 + lane) * 16;
#pragma unroll
        for (int m = 0; m < 16; m++) rp[m] = accD[m];
    }
    __syncthreads();
    if (tid < 128) {
        int k2 = tid >> 4, m = tid & 15;
        u64 s0 = 0ull, s1 = 0ull;
#pragma unroll
        for (int w = 0; w < 8; w += 2) {
            s0 = fadd2(red[(w * 8 + k2) * 16 + m], s0);
            s1 = fadd2(red[((w + 1) * 8 + k2) * 16 + m], s1);
        }
        float R, I; upk(fadd2(s0, s1), R, I);
        size_t o = (((size_t)j * 4 + b) * 16 + m) * 512 + cg * 8 + k2;
        DfR[o] = R; DfI[o] = I;
    }
    __syncthreads();
    if (lane < 8) {
        u64* rp = red + (warp * 8 + lane) * 16;
#pragma unroll
        for (int m = 0; m < 16; m++) rp[m] = accS[m];
    }
    __syncthreads();
    if (tid < 128) {
        int k2 = tid >> 4, m = tid & 15;
        u64 s0 = 0ull, s1 = 0ull;
#pragma unroll
        for (int w = 0; w < 8; w += 2) {
            s0 = fadd2(red[(w * 8 + k2) * 16 + m], s0);
            s1 = fadd2(red[((w + 1) * 8 + k2) * 16 + m], s1);
        }
        float R, I; upk(fadd2(s0, s1), R, I);
        size_t o = (((size_t)j * 4 + b) * 16 + m) * 512 + cg * 8 + k2;
        SfR[o] = R; SfI[o] = I;
    }
    __syncthreads();
}

__global__ void __launch_bounds__(256, 2) decomp_kernel(
    const float* __restrict__ vT, const u64* __restrict__ twF,
    const float* __restrict__ ec_s, const float* __restrict__ ec_d,
    float* __restrict__ DfR, float* __restrict__ DfI,
    float* __restrict__ SfR, float* __restrict__ SfI,
    float* __restrict__ coarse)
{
    extern __shared__ float sm[];
    float* bufB = sm;
    float* bufC = sm + 16384;
    u64* red = (u64*)(sm + 24576);
    u64* coef = red;
    u64* tws = (u64*)(sm + 26624);

    int tid = threadIdx.x;
    int cg = blockIdx.x, b = blockIdx.y;
    int t_lane = tid >> 3, k = tid & 7;

    if (tid < 128) coef[tid] = pk(ec_d[tid], ec_s[tid]);
    __syncthreads();

    const float* gin = vT + (size_t)(b * 64 + cg) * (NLEN * 8);
    u64 accD[16], accS[16];

    {
#pragma unroll
        for (int m = 0; m < 16; m++) { accD[m] = 0ull; accS[m] = 0ull; }
        decomp_level(gin, bufB, coef, twF, tws, 2048, t_lane, k, tid, accD, accS);
        decomp_reduce(accD, accS, red, tid, 0, b, cg, DfR, DfI, SfR, SfI);
        if (tid < 128) coef[tid] = pk(ec_d[tid], ec_s[tid]);
        __syncthreads();
    }

    float* in = bufB;
    float* out = bufC;
    for (int j = 1; j < NLVL; j++) {
        int Lout = 2048 >> j;
        const u64* twp = twF + 16 * (4096 - (4096 >> j));
#pragma unroll
        for (int m = 0; m < 16; m++) { accD[m] = 0ull; accS[m] = 0ull; }
        decomp_level(in, out, coef, twp, tws, Lout, t_lane, k, tid, accD, accS);
        decomp_reduce(accD, accS, red, tid, j, b, cg, DfR, DfI, SfR, SfI);
        if (tid < 128) coef[tid] = pk(ec_d[tid], ec_s[tid]);
        __syncthreads();
        float* tmp = in; in = out; out = tmp;
    }
    if (tid < 16)
        coarse[(b * 2 + (tid >> 3)) * 512 + cg * 8 + (tid & 7)] = in[8 * (tid >> 3) + (tid & 7)];
}

// ---------------- spectral mode mixing (o-tile 32, 256 thr, multi-CTA/SM phase overlap) ----------------
__global__ void __launch_bounds__(256, 2) mix_kernel(
    const float* __restrict__ Wt,
    const float* __restrict__ DfR, const float* __restrict__ DfI,
    const float* __restrict__ SfR, const float* __restrict__ SfI,
    float* __restrict__ UdFR, float* __restrict__ UdFI,
    float* __restrict__ UsFR, float* __restrict__ UsFI)
{
    int m = blockIdx.x;
    int o0 = blockIdx.y * 32;
    int tx = threadIdx.x & 31;
    int ty = threadIdx.x >> 5;     // 0..7

    __shared__ float wS[6][16][32];    // 12 KB
    __shared__ u64 xP[48][16][4];      // 24 KB, [r][ii][comp]

    u64 aUd[6], aUs[6];
#pragma unroll
    for (int r = 0; r < 6; r++) { aUd[r] = 0ull; aUs[r] = 0ull; }

    for (int i0 = 0; i0 < 512; i0 += 16) {
        __syncthreads();
        for (int idx = threadIdx.x; idx < 6 * 16 * 32; idx += 256) {
            int arr = idx >> 9; int rem = idx & 511; int ii = rem >> 5; int oo = rem & 31;
            wS[arr][ii][oo] = Wt[((size_t)arr * 16 + m) * 262144 + (size_t)(i0 + ii) * 512 + o0 + oo];
        }
        for (int idx = threadIdx.x; idx < 48 * 16 * 4; idx += 256) {
            int comp = idx / 768; int rem = idx - comp * 768; int r = rem >> 4; int ii = rem & 15;
            const float* src = (comp == 0) ? DfR : (comp == 1) ? DfI : (comp == 2) ? SfR : SfI;
            float v = (r < 44) ? src[((size_t)r * 16 + m) * 512 + i0 + ii] : 0.f;
            xP[r][ii][comp] = pk(v, v);
        }
        __syncthreads();
#pragma unroll
        for (int ii = 0; ii < 16; ii++) {
            float ar = wS[0][ii][tx], ai = wS[1][ii][tx];
            float br = wS[2][ii][tx], bi = wS[3][ii][tx];
            float cr = wS[4][ii][tx], ci = wS[5][ii][tx];
            u64 wa  = pk(ar, ai),  wan = pk(-ai, ar);
            u64 wb  = pk(br, bi),  wbn = pk(-bi, br);
            u64 wc  = pk(cr, ci),  wcn = pk(-ci, cr);
#pragma unroll
            for (int rr = 0; rr < 6; rr++) {
                int r = ty + rr * 8;
                const ulonglong2* xp2 = (const ulonglong2*)&xP[r][ii][0];
                ulonglong2 xd = xp2[0];   // (dd, di)
                ulonglong2 xs = xp2[1];   // (ss, si)
                aUd[rr] = f2(xd.x, wa, f2(xd.y, wan, f2(xs.x, wb, f2(xs.y, wbn, aUd[rr]))));
                aUs[rr] = f2(xd.x, wc, f2(xd.y, wcn, aUs[rr]));
            }
        }
    }
#pragma unroll
    for (int rr = 0; rr < 6; rr++) {
        int r = ty + rr * 8;
        if (r < 44) {
            size_t idx = ((size_t)r * 16 + m) * 512 + o0 + tx;
            float x, y;
            upk(aUd[rr], x, y); UdFR[idx] = x; UdFI[idx] = y;
            upk(aUs[rr], x, y); UsFR[idx] = x; UsFI[idx] = y;
        }
    }
}

// ---------------- recon level (aout != null => write bf16 split directly) ----------------
__device__ __forceinline__ void recon_level(
    const float* in, float* out, const u64* rcoef, const u64* __restrict__ twp,
    u64* tws,
    const float* __restrict__ UdFR, const float* __restrict__ UdFI,
    const float* __restrict__ UsFR, const float* __restrict__ UsFI,
    size_t specBase, int l, int nyq, float invL, int tmax,
    int t_lane, int k, int lane, int tid, __nv_bfloat16* aout)
{
    u64 vUd[16], vUs[16];
#pragma unroll
    for (int m = 0; m < 16; m++) {
        if (m < l) {
            size_t o = specBase + (size_t)m * 512;
            bool spec = (m == 0) || (nyq && m == l - 1);
            float sc = (spec ? 1.f : 2.f) * invL;
            vUd[m] = pk(sc * UdFR[o], spec ? 0.f : -sc * UdFI[o]);
            vUs[m] = pk(sc * UsFR[o], spec ? 0.f : -sc * UsFI[o]);
        } else { vUd[m] = 0ull; vUs[m] = 0ull; }
    }
    int base = lane & 24;
    int ntiles = (tmax + 31) >> 5;
    int pr = tid >> 3, pc = (tid & 7) * 2;
    ulonglong2 pre = make_ulonglong2(0ull, 0ull);
    if (pr < tmax) pre = __ldg((const ulonglong2*)(twp + (size_t)pr * 16 + pc));

    for (int tile = 0; tile < ntiles; tile++) {
        __syncthreads();
        tws[pr * TWS_STRIDE + pc] = pre.x;
        tws[pr * TWS_STRIDE + pc + 1] = pre.y;
        __syncthreads();
        int tn = ((tile + 1) << 5) + pr;
        if (tile + 1 < ntiles && tn < tmax)
            pre = __ldg((const ulonglong2*)(twp + (size_t)tn * 16 + pc));

        int t = (tile << 5) + t_lane;
        bool act = (t < tmax);
        int tc = act ? t : 0;
        const ulonglong2* tp2 = (const ulonglong2*)(tws + (act ? t_lane : 0) * TWS_STRIDE);
        u64 u0 = 0ull, u1 = 0ull, u2 = 0ull, u3 = 0ull;
        u64 s0 = 0ull, s1 = 0ull, s2 = 0ull, s3 = 0ull;
#pragma unroll
        for (int mp = 0; mp < 8; mp += 2) {
            ulonglong2 wA = tp2[mp], wB = tp2[mp + 1];
            int m = mp * 2;
            u0 = f2(wA.x, vUd[m + 0], u0);
            u1 = f2(wA.y, vUd[m + 1], u1);
            u2 = f2(wB.x, vUd[m + 2], u2);
            u3 = f2(wB.y, vUd[m + 3], u3);
            s0 = f2(wA.x, vUs[m + 0], s0);
            s1 = f2(wA.y, vUs[m + 1], s1);
            s2 = f2(wB.x, vUs[m + 2], s2);
            s3 = f2(wB.y, vUs[m + 3], s3);
        }
        u64 aU = fadd2(fadd2(u0, u1), fadd2(u2, u3));
        u64 aS = fadd2(fadd2(s0, s1), fadd2(s2, s3));
        float ux, uy, sx, sy; upk(aU, ux, uy); upk(aS, sx, sy);
        float ud = ux + uy;
        float vs = in[8 * tc + k] + (sx + sy);
        float vsg[8], udg[8];
#pragma unroll
        for (int kk = 0; kk < 8; kk++) vsg[kk] = __shfl_sync(0xffffffffu, vs, base | kk);
#pragma unroll
        for (int kk = 0; kk < 8; kk++) udg[kk] = __shfl_sync(0xffffffffu, ud, base | kk);
        u64 c0 = 0ull, c1 = 0ull, c2 = 0ull, c3 = 0ull;
#pragma unroll
        for (int kk = 0; kk < 8; kk += 4) {
            c0 = f2(pk(vsg[kk + 0], vsg[kk + 0]), rcoef[(kk + 0) * 8 + k], c0);
            c1 = f2(pk(vsg[kk + 1], vsg[kk + 1]), rcoef[(kk + 1) * 8 + k], c1);
            c2 = f2(pk(vsg[kk + 2], vsg[kk + 2]), rcoef[(kk + 2) * 8 + k], c2);
            c3 = f2(pk(vsg[kk + 3], vsg[kk + 3]), rcoef[(kk + 3) * 8 + k], c3);
        }
#pragma unroll
        for (int kk = 0; kk < 8; kk += 4) {
            c0 = f2(pk(udg[kk + 0], udg[kk + 0]), rcoef[(8 + kk + 0) * 8 + k], c0);
            c1 = f2(pk(udg[kk + 1], udg[kk + 1]), rcoef[(8 + kk + 1) * 8 + k], c1);
            c2 = f2(pk(udg[kk + 2], udg[kk + 2]), rcoef[(8 + kk + 2) * 8 + k], c2);
            c3 = f2(pk(udg[kk + 3], udg[kk + 3]), rcoef[(8 + kk + 3) * 8 + k], c3);
        }
        u64 acc = fadd2(fadd2(c0, c1), fadd2(c2, c3));
        if (act) {
            float xe, xo; upk(acc, xe, xo);
            if (aout) {
                __nv_bfloat16 h0 = __float2bfloat16(xe);
                __nv_bfloat16 l0 = __float2bfloat16(xe - __bfloat162float(h0));
                __nv_bfloat16 h1 = __float2bfloat16(xo);
                __nv_bfloat16 l1 = __float2bfloat16(xo - __bfloat162float(h1));
                size_t r0 = (size_t)(2 * t) * 1536;
                size_t r1 = r0 + 1536;
                aout[r0] = h0; aout[r0 + 512] = h0; aout[r0 + 1024] = l0;
                aout[r1] = h1; aout[r1 + 512] = h1; aout[r1 + 1024] = l1;
            } else {
                out[16 * t + k] = xe;
                out[16 * t + 8 + k] = xo;
            }
        }
    }
}

__global__ void __launch_bounds__(256, 2) recon_fused(
    const float* __restrict__ coarse, const u64* __restrict__ twI,
    const float* __restrict__ rc_e, const float* __restrict__ rc_o,
    const float* __restrict__ T0_w, const float* __restrict__ T0_b,
    const float* __restrict__ UdFR, const float* __restrict__ UdFI,
    const float* __restrict__ UsFR, const float* __restrict__ UsFI,
    __nv_bfloat16* __restrict__ Ax)
{
    extern __shared__ float sm[];
    float* bufB = sm;
    float* bufC = sm + 16384;
    u64* rcoef = (u64*)(sm + 24576);
    u64* tws = (u64*)(sm + 24832);

    __shared__ float cv[16];

    int tid = threadIdx.x;
    int cg = blockIdx.x, b = blockIdx.y;
    int t_lane = tid >> 3, k = tid & 7, lane = tid & 31;

    if (tid < 128) rcoef[tid] = pk(rc_e[tid], rc_o[tid]);
    if (tid < 16) cv[tid] = coarse[(b * 2 + (tid >> 3)) * 512 + cg * 8 + (tid & 7)];
    __syncthreads();
    if (tid < 16) {
        int tt = tid >> 3, kk = tid & 7;
        float s = T0_b[kk];
#pragma unroll
        for (int kp = 0; kp < 8; kp++) s += T0_w[kk * 8 + kp] * cv[tt * 8 + kp];
        bufB[tid] = s;
    }
    __syncthreads();

    float* in = bufB;
    float* out = bufC;
    for (int i = NLVL - 1; i >= 1; i--) {
        int Lc = 2048 >> i;
        int nf = (Lc >> 1) + 1;
        int l = nf < 16 ? nf : 16;
        int nyq = (l == nf);
        const u64* twp = twI + 16 * (4096 - (4096 >> i));
        size_t specBase = (((size_t)i * 4 + b) * 16) * 512 + cg * 8 + k;
        recon_level(in, out, rcoef, twp, tws, UdFR, UdFI, UsFR, UsFI,
                    specBase, l, nyq, 1.f / (float)Lc, Lc, t_lane, k, lane, tid, (__nv_bfloat16*)0);
        __syncthreads();
        float* tmp = in; in = out; out = tmp;
    }
    // level 0: write bf16 split operand directly (only t < 1536 -> rows < 3072)
    {
        __nv_bfloat16* aout = Ax + (size_t)(b * LSEQ) * 1536 + cg * 8 + k;
        size_t specBase = (((size_t)0 * 4 + b) * 16) * 512 + cg * 8 + k;
        recon_level(in, out, rcoef, twI, tws, UdFR, UdFI, UsFR, UsFI,
                    specBase, 16, 0, 1.f / 2048.f, 1536, t_lane, k, lane, tid, aout);
    }
}

// ---------------- host orchestration ----------------
extern "C" void kernel_launch(void* const* d_in, const int* in_sizes, int n_in,
                              void* d_out, int out_size)
{
    const float* x     = (const float*)d_in[0];
    const float* Lk0_w = (const float*)d_in[1];
    const float* Lk0_b = (const float*)d_in[2];
    const float* Lk1_w = (const float*)d_in[3];
    const float* Lk1_b = (const float*)d_in[4];
    const float* T0_w  = (const float*)d_in[5];
    const float* T0_b  = (const float*)d_in[6];
    const float* Ar    = (const float*)d_in[7];
    const float* Ai    = (const float*)d_in[8];
    const float* Br    = (const float*)d_in[9];
    const float* Bi    = (const float*)d_in[10];
    const float* Cr    = (const float*)d_in[11];
    const float* Ci    = (const float*)d_in[12];
    const float* ec_s  = (const float*)d_in[13];
    const float* ec_d  = (const float*)d_in[14];
    const float* rc_e  = (const float*)d_in[15];
    const float* rc_o  = (const float*)d_in[16];

    float *vT, *coarse, *DfR, *DfI, *SfR, *SfI, *UdFR, *UdFI, *UsFR, *UsFI, *Wt;
    u64 *twF, *twI;
    __nv_bfloat16 *Ax, *Wx0, *Wx1;
    cudaGetSymbolAddress((void**)&vT, g_vT);
    cudaGetSymbolAddress((void**)&coarse, g_coarse);
    cudaGetSymbolAddress((void**)&DfR, g_DfR);
    cudaGetSymbolAddress((void**)&DfI, g_DfI);
    cudaGetSymbolAddress((void**)&SfR, g_SfR);
    cudaGetSymbolAddress((void**)&SfI, g_SfI);
    cudaGetSymbolAddress((void**)&UdFR, g_UdFR);
    cudaGetSymbolAddress((void**)&UdFI, g_UdFI);
    cudaGetSymbolAddress((void**)&UsFR, g_UsFR);
    cudaGetSymbolAddress((void**)&UsFI, g_UsFI);
    cudaGetSymbolAddress((void**)&Wt, g_Wt);
    cudaGetSymbolAddress((void**)&twF, g_twF);
    cudaGetSymbolAddress((void**)&twI, g_twI);
    cudaGetSymbolAddress((void**)&Ax, g_Ax);
    cudaGetSymbolAddress((void**)&Wx0, g_Wx0);
    cudaGetSymbolAddress((void**)&Wx1, g_Wx1);

    const int DECOMP_SMEM = 111104;
    const int RECON_SMEM  = 103936;
    cudaFuncSetAttribute(decomp_kernel, cudaFuncAttributeMaxDynamicSharedMemorySize, DECOMP_SMEM);
    cudaFuncSetAttribute(recon_fused, cudaFuncAttributeMaxDynamicSharedMemorySize, RECON_SMEM);

    twiddle_kernel<<<dim3(128, NLVL), 256>>>(twF, twI);
    transpose_w<<<dim3(4096, 6), 256>>>(Ar, Ai, Br, Bi, Cr, Ci, Wt);
    split_w_kernel<<<dim3(128, 2), 256>>>(Lk0_w, Lk1_w, Wx0, Wx1);
    split_x_kernel<<<4096, 256>>>(x, Ax);

    // Lk0 via warp-MMA tensor cores -> vT
    mma_gemm<<<dim3(4, 128), 256>>>(Ax, Wx0, Lk0_b, vT, 0);

    decomp_kernel<<<dim3(64, NB), 256, DECOMP_SMEM>>>(vT, twF, ec_s, ec_d,
                                                      DfR, DfI, SfR, SfI, coarse);

    // mix: o-tile 32 -> 256 CTAs, 2+ CTAs/SM for load/compute phase overlap
    mix_kernel<<<dim3(16, 16), 256>>>(Wt, DfR, DfI, SfR, SfI, UdFR, UdFI, UsFR, UsFI);

    // fused recon writes the bf16 split GEMM operand directly into Ax
    recon_fused<<<dim3(64, NB), 256, RECON_SMEM>>>(coarse, twI, rc_e, rc_o, T0_w, T0_b,
                                                   UdFR, UdFI, UsFR, UsFI, Ax);

    // Lk1 via warp-MMA tensor cores -> d_out
    mma_gemm<<<dim3(4, 96), 256>>>(Ax, Wx1, Lk1_b, (float*)d_out, 1);
}

// round 17
// speedup vs baseline: 1.1355x; 1.1214x over previous
#include <cuda_runtime.h>
#include <cuda_bf16.h>
#include <math.h>

#define NB 4
#define NLEN 4096
#define LSEQ 3072
#define NLVL 11
#define TWO_PI 6.28318530717958647692f

typedef unsigned long long u64;

// ---------------- f32x2 helpers ----------------
__device__ __forceinline__ u64 pk(float x, float y) {
    u64 r; asm("mov.b64 %0, {%1, %2};" : "=l"(r) : "f"(x), "f"(y)); return r;
}
__device__ __forceinline__ void upk(u64 v, float& x, float& y) {
    asm("mov.b64 {%0, %1}, %2;" : "=f"(x), "=f"(y) : "l"(v));
}
__device__ __forceinline__ u64 f2(u64 a, u64 b, u64 c) {
    u64 d; asm("fma.rn.f32x2 %0, %1, %2, %3;" : "=l"(d) : "l"(a), "l"(b), "l"(c)); return d;
}
__device__ __forceinline__ u64 fadd2(u64 a, u64 b) {
    u64 d; asm("add.rn.f32x2 %0, %1, %2;" : "=l"(d) : "l"(a), "l"(b)); return d;
}

// ---------------- device scratch ----------------
__device__ float g_vT[(size_t)NB * 64 * NLEN * 8];   // [b][c][t][k]
__device__ float g_coarse[NB * 2 * 512];

#define SPEC_SZ (NLVL * NB * 16 * 512)
__device__ float g_DfR[SPEC_SZ];
__device__ float g_DfI[SPEC_SZ];
__device__ float g_SfR[SPEC_SZ];
__device__ float g_SfI[SPEC_SZ];
__device__ float g_UdFR[SPEC_SZ];
__device__ float g_UdFI[SPEC_SZ];
__device__ float g_UsFR[SPEC_SZ];
__device__ float g_UsFI[SPEC_SZ];

__device__ float g_Wt[(size_t)6 * 16 * 512 * 512];
__device__ u64 g_twF[16 * 4096];
__device__ u64 g_twI[16 * 4096];

// bf16 split operands, K concatenated to 1536: A' = [Ah|Ah|Al], W' = [Wh|Wl|Wh]
__device__ __nv_bfloat16 g_Ax[(size_t)16384 * 1536];
__device__ __nv_bfloat16 g_Wx0[512 * 1536];
__device__ __nv_bfloat16 g_Wx1[512 * 1536];

// ---------------- twiddle tables ----------------
__global__ void twiddle_kernel(u64* __restrict__ twF, u64* __restrict__ twI) {
    int j = blockIdx.y;
    int Lc = NLEN >> (j + 1);
    int idx = blockIdx.x * 256 + threadIdx.x;
    if (idx >= Lc * 16) return;
    int t = idx >> 4, m = idx & 15;
    int toff = 16 * (4096 - (4096 >> j));
    float ang = (TWO_PI / (float)Lc) * (float)(m * t);
    float sv, cv;
    sincosf(ang, &sv, &cv);
    twF[toff + idx] = pk(cv, -sv);
    twI[toff + idx] = pk(cv, sv);
}

// ---------------- bf16 split kernels ----------------
__device__ __forceinline__ void split8(const float* vv, uint4& H, uint4& L) {
    __align__(16) __nv_bfloat16 h[8];
    __align__(16) __nv_bfloat16 l[8];
#pragma unroll
    for (int k = 0; k < 8; k++) {
        h[k] = __float2bfloat16(vv[k]);
        l[k] = __float2bfloat16(vv[k] - __bfloat162float(h[k]));
    }
    H = *(uint4*)h;
    L = *(uint4*)l;
}

__global__ void split_x_kernel(const float* __restrict__ x, __nv_bfloat16* __restrict__ Ax)
{
    int idx = blockIdx.x * 256 + threadIdx.x;      // 16384*64
    int row = idx >> 6, c8 = idx & 63;
    int b = row >> 12, t = row & 4095;
    int srcRow = b * LSEQ + (t < LSEQ ? t : t - LSEQ);
    const float4* s = (const float4*)(x + (size_t)srcRow * 512 + c8 * 8);
    float4 v0 = s[0], v1 = s[1];
    float vv[8] = {v0.x, v0.y, v0.z, v0.w, v1.x, v1.y, v1.z, v1.w};
    uint4 H, L; split8(vv, H, L);
    size_t o = (size_t)row * 1536 + c8 * 8;
    *(uint4*)(Ax + o) = H;
    *(uint4*)(Ax + o + 512) = H;
    *(uint4*)(Ax + o + 1024) = L;
}

__global__ void split_w_kernel(const float* __restrict__ W0, const float* __restrict__ W1,
                               __nv_bfloat16* __restrict__ Wx0, __nv_bfloat16* __restrict__ Wx1)
{
    int idx = blockIdx.x * 256 + threadIdx.x;      // 512*64
    const float* W = blockIdx.y ? W1 : W0;
    __nv_bfloat16* Wx = blockIdx.y ? Wx1 : Wx0;
    int row = idx >> 6, c8 = idx & 63;
    const float4* s = (const float4*)(W + (size_t)row * 512 + c8 * 8);
    float4 v0 = s[0], v1 = s[1];
    float vv[8] = {v0.x, v0.y, v0.z, v0.w, v1.x, v1.y, v1.z, v1.w};
    uint4 H, L; split8(vv, H, L);
    size_t o = (size_t)row * 1536 + c8 * 8;
    *(uint4*)(Wx + o) = H;        // Wh
    *(uint4*)(Wx + o + 512) = L;  // Wl
    *(uint4*)(Wx + o + 1024) = H; // Wh
}

// ---------------- warp-MMA bf16 GEMM ----------------
__device__ __forceinline__ void mma_bf16(float* c, const unsigned* a, const unsigned* b) {
    asm volatile("mma.sync.aligned.m16n8k16.row.col.f32.bf16.bf16.f32 "
        "{%0,%1,%2,%3}, {%4,%5,%6,%7}, {%8,%9}, {%0,%1,%2,%3};"
        : "+f"(c[0]), "+f"(c[1]), "+f"(c[2]), "+f"(c[3])
        : "r"(a[0]), "r"(a[1]), "r"(a[2]), "r"(a[3]), "r"(b[0]), "r"(b[1]));
}

#define KCN 48   // 1536 / 32

__global__ void __launch_bounds__(256) mma_gemm(
    const __nv_bfloat16* __restrict__ A,   // [M][1536]
    const __nv_bfloat16* __restrict__ B,   // [512][1536]
    const float* __restrict__ bias, float* __restrict__ C, int mode)
{
    __shared__ __nv_bfloat16 As[2][128][40];
    __shared__ __nv_bfloat16 Bs[2][128][40];
    int tid = threadIdx.x, lane = tid & 31, wid = tid >> 5;
    int wm = (wid & 3) * 32, wn = (wid >> 2) * 64;
    int m0 = blockIdx.y * 128, nb0 = blockIdx.x * 128;
    int g = lane >> 2, q = lane & 3;
    int r0 = tid >> 2, cq = (tid & 3) * 8;

    uint4 pa0, pa1, pb0, pb1;
#define G2R(kc) do { \
        pa0 = *(const uint4*)(A + (size_t)(m0 + r0) * 1536 + (kc) * 32 + cq); \
        pa1 = *(const uint4*)(A + (size_t)(m0 + r0 + 64) * 1536 + (kc) * 32 + cq); \
        pb0 = *(const uint4*)(B + (size_t)(nb0 + r0) * 1536 + (kc) * 32 + cq); \
        pb1 = *(const uint4*)(B + (size_t)(nb0 + r0 + 64) * 1536 + (kc) * 32 + cq); \
    } while (0)
#define R2S(buf) do { \
        *(uint4*)&As[buf][r0][cq] = pa0; \
        *(uint4*)&As[buf][r0 + 64][cq] = pa1; \
        *(uint4*)&Bs[buf][r0][cq] = pb0; \
        *(uint4*)&Bs[buf][r0 + 64][cq] = pb1; \
    } while (0)

    float acc[2][8][4];
#pragma unroll
    for (int mb = 0; mb < 2; mb++)
#pragma unroll
        for (int nk = 0; nk < 8; nk++)
#pragma unroll
            for (int i = 0; i < 4; i++) acc[mb][nk][i] = 0.f;

    G2R(0);
    R2S(0);
    __syncthreads();

    for (int kc = 0; kc < KCN; kc++) {
        int cur = kc & 1;
        if (kc + 1 < KCN) G2R(kc + 1);
#pragma unroll
        for (int ks = 0; ks < 2; ks++) {
            unsigned af[2][4], bfr[8][2];
#pragma unroll
            for (int mb = 0; mb < 2; mb++) {
                const __nv_bfloat16* ap = &As[cur][wm + mb * 16 + g][ks * 16 + q * 2];
                af[mb][0] = *(const unsigned*)ap;
                af[mb][1] = *(const unsigned*)(ap + 320);
                af[mb][2] = *(const unsigned*)(ap + 8);
                af[mb][3] = *(const unsigned*)(ap + 328);
            }
#pragma unroll
            for (int nk = 0; nk < 8; nk++) {
                const __nv_bfloat16* bp = &Bs[cur][wn + nk * 8 + g][ks * 16 + q * 2];
                bfr[nk][0] = *(const unsigned*)bp;
                bfr[nk][1] = *(const unsigned*)(bp + 8);
            }
#pragma unroll
            for (int mb = 0; mb < 2; mb++)
#pragma unroll
                for (int nk = 0; nk < 8; nk++)
                    mma_bf16(acc[mb][nk], af[mb], bfr[nk]);
        }
        if (kc + 1 < KCN) {
            __syncthreads();
            R2S(cur ^ 1);
            __syncthreads();
        }
    }

#pragma unroll
    for (int mb = 0; mb < 2; mb++) {
        int r = m0 + wm + mb * 16 + g;
#pragma unroll
        for (int nk = 0; nk < 8; nk++) {
            int c = nb0 + wn + nk * 8 + q * 2;
            float b0v = bias[c], b1v = bias[c + 1];
            float2 v01 = make_float2(acc[mb][nk][0] + b0v, acc[mb][nk][1] + b1v);
            float2 v23 = make_float2(acc[mb][nk][2] + b0v, acc[mb][nk][3] + b1v);
            if (mode == 0) {
                int b = r >> 12, t = r & 4095;
                float* base = C + ((size_t)(b * 64 + (c >> 3)) * NLEN) * 8 + (c & 7);
                *(float2*)(base + (size_t)t * 8) = v01;
                *(float2*)(base + (size_t)(t + 8) * 8) = v23;
            } else {
                *(float2*)(C + (size_t)r * 512 + c) = v01;
                *(float2*)(C + (size_t)(r + 8) * 512 + c) = v23;
            }
        }
    }
#undef G2R
#undef R2S
}

// ---------------- weight transpose ----------------
__global__ void transpose_w(const float* __restrict__ Ar, const float* __restrict__ Ai,
                            const float* __restrict__ Br, const float* __restrict__ Bi,
                            const float* __restrict__ Cr, const float* __restrict__ Ci,
                            float* __restrict__ Wt)
{
    const float* src;
    switch (blockIdx.y) {
        case 0: src = Ar; break; case 1: src = Ai; break; case 2: src = Br; break;
        case 3: src = Bi; break; case 4: src = Cr; break; default: src = Ci; break;
    }
    float* dst = Wt + (size_t)blockIdx.y * 16 * 262144;
    int io0 = blockIdx.x * 64;
    __shared__ float sm2[64][17];
    int t = threadIdx.x;
    {
        int ioL = t >> 2; int mq = (t & 3) * 4;
        float4 v = *(const float4*)(src + (size_t)(io0 + ioL) * 16 + mq);
        sm2[ioL][mq] = v.x; sm2[ioL][mq + 1] = v.y; sm2[ioL][mq + 2] = v.z; sm2[ioL][mq + 3] = v.w;
    }
    __syncthreads();
    {
        int m = t >> 4; int g = (t & 15) * 4;
        float* d2 = dst + (size_t)m * 262144 + io0 + g;
        d2[0] = sm2[g][m]; d2[1] = sm2[g + 1][m]; d2[2] = sm2[g + 2][m]; d2[3] = sm2[g + 3][m];
    }
}

#define TWS_STRIDE 18

// ---------------- decomposition level ----------------
__device__ __forceinline__ void decomp_level(
    const float* in, float* out, const u64* coef, const u64* __restrict__ twp,
    u64* tws, int Lout, int t_lane, int k, int tid, u64* accD, u64* accS)
{
    int ntiles = (Lout + 31) >> 5;
    int pr = tid >> 3, pc = (tid & 7) * 2;
    ulonglong2 pre = make_ulonglong2(0ull, 0ull);
    if (pr < Lout) pre = __ldg((const ulonglong2*)(twp + (size_t)pr * 16 + pc));

    for (int tile = 0; tile < ntiles; tile++) {
        __syncthreads();
        tws[pr * TWS_STRIDE + pc] = pre.x;
        tws[pr * TWS_STRIDE + pc + 1] = pre.y;
        __syncthreads();
        int tn = ((tile + 1) << 5) + pr;
        if (tile + 1 < ntiles && tn < Lout)
            pre = __ldg((const ulonglong2*)(twp + (size_t)tn * 16 + pc));

        int t = (tile << 5) + t_lane;
        if (t < Lout) {
            const float4* p = (const float4*)(in + 16 * t);
            float4 q0 = p[0], q1 = p[1], q2 = p[2], q3 = p[3];
            float xa[16] = {q0.x, q0.y, q0.z, q0.w, q1.x, q1.y, q1.z, q1.w,
                            q2.x, q2.y, q2.z, q2.w, q3.x, q3.y, q3.z, q3.w};
            u64 c0 = 0ull, c1 = 0ull, c2 = 0ull, c3 = 0ull;
#pragma unroll
            for (int kk = 0; kk < 16; kk += 4) {
                c0 = f2(pk(xa[kk + 0], xa[kk + 0]), coef[(kk + 0) * 8 + k], c0);
                c1 = f2(pk(xa[kk + 1], xa[kk + 1]), coef[(kk + 1) * 8 + k], c1);
                c2 = f2(pk(xa[kk + 2], xa[kk + 2]), coef[(kk + 2) * 8 + k], c2);
                c3 = f2(pk(xa[kk + 3], xa[kk + 3]), coef[(kk + 3) * 8 + k], c3);
            }
            u64 ds = fadd2(fadd2(c0, c1), fadd2(c2, c3));
            float dv, sv; upk(ds, dv, sv);
            out[8 * t + k] = sv;
            u64 dd = pk(dv, dv), ss = pk(sv, sv);
            const ulonglong2* tp2 = (const ulonglong2*)(tws + t_lane * TWS_STRIDE);
#pragma unroll
            for (int mp = 0; mp < 8; mp += 2) {
                ulonglong2 wA = tp2[mp], wB = tp2[mp + 1];
                int m = mp * 2;
                accD[m + 0] = f2(dd, wA.x, accD[m + 0]);
                accD[m + 1] = f2(dd, wA.y, accD[m + 1]);
                accD[m + 2] = f2(dd, wB.x, accD[m + 2]);
                accD[m + 3] = f2(dd, wB.y, accD[m + 3]);
                accS[m + 0] = f2(ss, wA.x, accS[m + 0]);
                accS[m + 1] = f2(ss, wA.y, accS[m + 1]);
                accS[m + 2] = f2(ss, wB.x, accS[m + 2]);
                accS[m + 3] = f2(ss, wB.y, accS[m + 3]);
            }
        }
    }
}

__device__ __forceinline__ void decomp_reduce(
    u64* accD, u64* accS, u64* red, int tid, int j, int b, int cg,
    float* __restrict__ DfR, float* __restrict__ DfI,
    float* __restrict__ SfR, float* __restrict__ SfI)
{
#pragma unroll
    for (int m = 0; m < 16; m++) {
        accD[m] = fadd2(__shfl_xor_sync(0xffffffffu, accD[m], 8), accD[m]);
        accD[m] = fadd2(__shfl_xor_sync(0xffffffffu, accD[m], 16), accD[m]);
        accS[m] = fadd2(__shfl_xor_sync(0xffffffffu, accS[m], 8), accS[m]);
        accS[m] = fadd2(__shfl_xor_sync(0xffffffffu, accS[m], 16), accS[m]);
    }
    int lane = tid & 31, warp = tid >> 5;
    __syncthreads();
    if (lane < 8) {
        u64* rp = red + (warp * 8 + lane) * 16;
#pragma unroll
        for (int m = 0; m < 16; m++) rp[m] = accD[m];
    }
    __syncthreads();
    if (tid < 128) {
        int k2 = tid >> 4, m = tid & 15;
        u64 s0 = 0ull, s1 = 0ull;
#pragma unroll
        for (int w = 0; w < 8; w += 2) {
            s0 = fadd2(red[(w * 8 + k2) * 16 + m], s0);
            s1 = fadd2(red[((w + 1) * 8 + k2) * 16 + m], s1);
        }
        float R, I; upk(fadd2(s0, s1), R, I);
        size_t o = (((size_t)j * 4 + b) * 16 + m) * 512 + cg * 8 + k2;
        DfR[o] = R; DfI[o] = I;
    }
    __syncthreads();
    if (lane < 8) {
        u64* rp = red + (warp * 8 + lane) * 16;
#pragma unroll
        for (int m = 0; m < 16; m++) rp[m] = accS[m];
    }
    __syncthreads();
    if (tid < 128) {
        int k2 = tid >> 4, m = tid & 15;
        u64 s0 = 0ull, s1 = 0ull;
#pragma unroll
        for (int w = 0; w < 8; w += 2) {
            s0 = fadd2(red[(w * 8 + k2) * 16 + m], s0);
            s1 = fadd2(red[((w + 1) * 8 + k2) * 16 + m], s1);
        }
        float R, I; upk(fadd2(s0, s1), R, I);
        size_t o = (((size_t)j * 4 + b) * 16 + m) * 512 + cg * 8 + k2;
        SfR[o] = R; SfI[o] = I;
    }
    __syncthreads();
}

__global__ void __launch_bounds__(256, 2) decomp_kernel(
    const float* __restrict__ vT, const u64* __restrict__ twF,
    const float* __restrict__ ec_s, const float* __restrict__ ec_d,
    float* __restrict__ DfR, float* __restrict__ DfI,
    float* __restrict__ SfR, float* __restrict__ SfI,
    float* __restrict__ coarse)
{
    extern __shared__ float sm[];
    float* bufB = sm;
    float* bufC = sm + 16384;
    u64* red = (u64*)(sm + 24576);
    u64* coef = red;
    u64* tws = (u64*)(sm + 26624);

    int tid = threadIdx.x;
    int cg = blockIdx.x, b = blockIdx.y;
    int t_lane = tid >> 3, k = tid & 7;

    if (tid < 128) coef[tid] = pk(ec_d[tid], ec_s[tid]);
    __syncthreads();

    const float* gin = vT + (size_t)(b * 64 + cg) * (NLEN * 8);
    u64 accD[16], accS[16];

    {
#pragma unroll
        for (int m = 0; m < 16; m++) { accD[m] = 0ull; accS[m] = 0ull; }
        decomp_level(gin, bufB, coef, twF, tws, 2048, t_lane, k, tid, accD, accS);
        decomp_reduce(accD, accS, red, tid, 0, b, cg, DfR, DfI, SfR, SfI);
        if (tid < 128) coef[tid] = pk(ec_d[tid], ec_s[tid]);
        __syncthreads();
    }

    float* in = bufB;
    float* out = bufC;
    for (int j = 1; j < NLVL; j++) {
        int Lout = 2048 >> j;
        const u64* twp = twF + 16 * (4096 - (4096 >> j));
#pragma unroll
        for (int m = 0; m < 16; m++) { accD[m] = 0ull; accS[m] = 0ull; }
        decomp_level(in, out, coef, twp, tws, Lout, t_lane, k, tid, accD, accS);
        decomp_reduce(accD, accS, red, tid, j, b, cg, DfR, DfI, SfR, SfI);
        if (tid < 128) coef[tid] = pk(ec_d[tid], ec_s[tid]);
        __syncthreads();
        float* tmp = in; in = out; out = tmp;
    }
    if (tid < 16)
        coarse[(b * 2 + (tid >> 3)) * 512 + cg * 8 + (tid & 7)] = in[8 * (tid >> 3) + (tid & 7)];
}

// ---------------- spectral mode mixing (reg-prefetch pipelined, split chains) ----------------
__global__ void __launch_bounds__(256, 2) mix_kernel(
    const float* __restrict__ Wt,
    const float* __restrict__ DfR, const float* __restrict__ DfI,
    const float* __restrict__ SfR, const float* __restrict__ SfI,
    float* __restrict__ UdFR, float* __restrict__ UdFI,
    float* __restrict__ UsFR, float* __restrict__ UsFI)
{
    int m = blockIdx.x;
    int o0 = blockIdx.y * 32;
    int tid = threadIdx.x;
    int tx = tid & 31;
    int ty = tid >> 5;     // 0..7

    __shared__ float wS[6][16][32];    // 12 KB
    __shared__ u64 xP[48][16][4];      // 24 KB, [r][ii][comp]

    // per-thread prefetch slots: 12 wS elements + 12 xP elements per chunk
    float wreg[12], xreg[12];
    // decode (constant per thread)
    int warr[12], wii, woo;
    wii = 0; woo = 0; (void)wii; (void)woo;
    int xcomp[12], xr[12], xii[12];
#pragma unroll
    for (int j = 0; j < 12; j++) {
        int idx = tid + j * 256;
        warr[j] = idx >> 9;
        int xidx = tid + j * 256;
        xcomp[j] = xidx / 768;
        int xrem = xidx - xcomp[j] * 768;
        xr[j] = xrem >> 4;
        xii[j] = xrem & 15;
    }

    u64 aU1[6], aU2[6], aUs[6];
#pragma unroll
    for (int r = 0; r < 6; r++) { aU1[r] = 0ull; aU2[r] = 0ull; aUs[r] = 0ull; }

    // prefetch chunk 0
#pragma unroll
    for (int j = 0; j < 12; j++) {
        int idx = tid + j * 256;
        int rem = idx & 511; int ii = rem >> 5; int oo = rem & 31;
        wreg[j] = __ldg(&Wt[((size_t)warr[j] * 16 + m) * 262144 + (size_t)ii * 512 + o0 + oo]);
        const float* src = (xcomp[j] == 0) ? DfR : (xcomp[j] == 1) ? DfI : (xcomp[j] == 2) ? SfR : SfI;
        xreg[j] = (xr[j] < 44) ? __ldg(&src[((size_t)xr[j] * 16 + m) * 512 + xii[j]]) : 0.f;
    }

    for (int c = 0; c < 32; c++) {
        __syncthreads();   // previous compute done; smem writable
#pragma unroll
        for (int j = 0; j < 12; j++) {
            int idx = tid + j * 256;
            int rem = idx & 511; int ii = rem >> 5; int oo = rem & 31;
            wS[warr[j]][ii][oo] = wreg[j];
            xP[xr[j]][xii[j]][xcomp[j]] = pk(xreg[j], xreg[j]);
        }
        __syncthreads();   // smem ready
        if (c + 1 < 32) {
            int i0 = (c + 1) * 16;
#pragma unroll
            for (int j = 0; j < 12; j++) {
                int idx = tid + j * 256;
                int rem = idx & 511; int ii = rem >> 5; int oo = rem & 31;
                wreg[j] = __ldg(&Wt[((size_t)warr[j] * 16 + m) * 262144 + (size_t)(i0 + ii) * 512 + o0 + oo]);
                const float* src = (xcomp[j] == 0) ? DfR : (xcomp[j] == 1) ? DfI : (xcomp[j] == 2) ? SfR : SfI;
                xreg[j] = (xr[j] < 44) ? __ldg(&src[((size_t)xr[j] * 16 + m) * 512 + i0 + xii[j]]) : 0.f;
            }
        }
#pragma unroll
        for (int ii = 0; ii < 16; ii++) {
            float ar = wS[0][ii][tx], ai = wS[1][ii][tx];
            float br = wS[2][ii][tx], bi = wS[3][ii][tx];
            float cr = wS[4][ii][tx], ci = wS[5][ii][tx];
            u64 wa  = pk(ar, ai),  wan = pk(-ai, ar);
            u64 wb  = pk(br, bi),  wbn = pk(-bi, br);
            u64 wc  = pk(cr, ci),  wcn = pk(-ci, cr);
#pragma unroll
            for (int rr = 0; rr < 6; rr++) {
                int r = ty + rr * 8;
                const ulonglong2* xp2 = (const ulonglong2*)&xP[r][ii][0];
                ulonglong2 xd = xp2[0];   // (dd, di)
                ulonglong2 xs = xp2[1];   // (ss, si)
                aU1[rr] = f2(xd.x, wa, f2(xd.y, wan, aU1[rr]));
                aU2[rr] = f2(xs.x, wb, f2(xs.y, wbn, aU2[rr]));
                aUs[rr] = f2(xd.x, wc, f2(xd.y, wcn, aUs[rr]));
            }
        }
    }
#pragma unroll
    for (int rr = 0; rr < 6; rr++) {
        int r = ty + rr * 8;
        if (r < 44) {
            size_t idx = ((size_t)r * 16 + m) * 512 + o0 + tx;
            float x, y;
            upk(fadd2(aU1[rr], aU2[rr]), x, y); UdFR[idx] = x; UdFI[idx] = y;
            upk(aUs[rr], x, y); UsFR[idx] = x; UsFI[idx] = y;
        }
    }
}

// ---------------- recon level (aout != null => write bf16 split directly) ----------------
__device__ __forceinline__ void recon_level(
    const float* in, float* out, const u64* rcoef, const u64* __restrict__ twp,
    u64* tws,
    const float* __restrict__ UdFR, const float* __restrict__ UdFI,
    const float* __restrict__ UsFR, const float* __restrict__ UsFI,
    size_t specBase, int l, int nyq, float invL, int tmax,
    int t_lane, int k, int lane, int tid, __nv_bfloat16* aout)
{
    u64 vUd[16], vUs[16];
#pragma unroll
    for (int m = 0; m < 16; m++) {
        if (m < l) {
            size_t o = specBase + (size_t)m * 512;
            bool spec = (m == 0) || (nyq && m == l - 1);
            float sc = (spec ? 1.f : 2.f) * invL;
            vUd[m] = pk(sc * UdFR[o], spec ? 0.f : -sc * UdFI[o]);
            vUs[m] = pk(sc * UsFR[o], spec ? 0.f : -sc * UsFI[o]);
        } else { vUd[m] = 0ull; vUs[m] = 0ull; }
    }
    int base = lane & 24;
    int ntiles = (tmax + 31) >> 5;
    int pr = tid >> 3, pc = (tid & 7) * 2;
    ulonglong2 pre = make_ulonglong2(0ull, 0ull);
    if (pr < tmax) pre = __ldg((const ulonglong2*)(twp + (size_t)pr * 16 + pc));

    for (int tile = 0; tile < ntiles; tile++) {
        __syncthreads();
        tws[pr * TWS_STRIDE + pc] = pre.x;
        tws[pr * TWS_STRIDE + pc + 1] = pre.y;
        __syncthreads();
        int tn = ((tile + 1) << 5) + pr;
        if (tile + 1 < ntiles && tn < tmax)
            pre = __ldg((const ulonglong2*)(twp + (size_t)tn * 16 + pc));

        int t = (tile << 5) + t_lane;
        bool act = (t < tmax);
        int tc = act ? t : 0;
        const ulonglong2* tp2 = (const ulonglong2*)(tws + (act ? t_lane : 0) * TWS_STRIDE);
        u64 u0 = 0ull, u1 = 0ull, u2 = 0ull, u3 = 0ull;
        u64 s0 = 0ull, s1 = 0ull, s2 = 0ull, s3 = 0ull;
#pragma unroll
        for (int mp = 0; mp < 8; mp += 2) {
            ulonglong2 wA = tp2[mp], wB = tp2[mp + 1];
            int m = mp * 2;
            u0 = f2(wA.x, vUd[m + 0], u0);
            u1 = f2(wA.y, vUd[m + 1], u1);
            u2 = f2(wB.x, vUd[m + 2], u2);
            u3 = f2(wB.y, vUd[m + 3], u3);
            s0 = f2(wA.x, vUs[m + 0], s0);
            s1 = f2(wA.y, vUs[m + 1], s1);
            s2 = f2(wB.x, vUs[m + 2], s2);
            s3 = f2(wB.y, vUs[m + 3], s3);
        }
        u64 aU = fadd2(fadd2(u0, u1), fadd2(u2, u3));
        u64 aS = fadd2(fadd2(s0, s1), fadd2(s2, s3));
        float ux, uy, sx, sy; upk(aU, ux, uy); upk(aS, sx, sy);
        float ud = ux + uy;
        float vs = in[8 * tc + k] + (sx + sy);
        float vsg[8], udg[8];
#pragma unroll
        for (int kk = 0; kk < 8; kk++) vsg[kk] = __shfl_sync(0xffffffffu, vs, base | kk);
#pragma unroll
        for (int kk = 0; kk < 8; kk++) udg[kk] = __shfl_sync(0xffffffffu, ud, base | kk);
        u64 c0 = 0ull, c1 = 0ull, c2 = 0ull, c3 = 0ull;
#pragma unroll
        for (int kk = 0; kk < 8; kk += 4) {
            c0 = f2(pk(vsg[kk + 0], vsg[kk + 0]), rcoef[(kk + 0) * 8 + k], c0);
            c1 = f2(pk(vsg[kk + 1], vsg[kk + 1]), rcoef[(kk + 1) * 8 + k], c1);
            c2 = f2(pk(vsg[kk + 2], vsg[kk + 2]), rcoef[(kk + 2) * 8 + k], c2);
            c3 = f2(pk(vsg[kk + 3], vsg[kk + 3]), rcoef[(kk + 3) * 8 + k], c3);
        }
#pragma unroll
        for (int kk = 0; kk < 8; kk += 4) {
            c0 = f2(pk(udg[kk + 0], udg[kk + 0]), rcoef[(8 + kk + 0) * 8 + k], c0);
            c1 = f2(pk(udg[kk + 1], udg[kk + 1]), rcoef[(8 + kk + 1) * 8 + k], c1);
            c2 = f2(pk(udg[kk + 2], udg[kk + 2]), rcoef[(8 + kk + 2) * 8 + k], c2);
            c3 = f2(pk(udg[kk + 3], udg[kk + 3]), rcoef[(8 + kk + 3) * 8 + k], c3);
        }
        u64 acc = fadd2(fadd2(c0, c1), fadd2(c2, c3));
        if (act) {
            float xe, xo; upk(acc, xe, xo);
            if (aout) {
                __nv_bfloat16 h0 = __float2bfloat16(xe);
                __nv_bfloat16 l0 = __float2bfloat16(xe - __bfloat162float(h0));
                __nv_bfloat16 h1 = __float2bfloat16(xo);
                __nv_bfloat16 l1 = __float2bfloat16(xo - __bfloat162float(h1));
                size_t r0 = (size_t)(2 * t) * 1536;
                size_t r1 = r0 + 1536;
                aout[r0] = h0; aout[r0 + 512] = h0; aout[r0 + 1024] = l0;
                aout[r1] = h1; aout[r1 + 512] = h1; aout[r1 + 1024] = l1;
            } else {
                out[16 * t + k] = xe;
                out[16 * t + 8 + k] = xo;
            }
        }
    }
}

__global__ void __launch_bounds__(256, 2) recon_fused(
    const float* __restrict__ coarse, const u64* __restrict__ twI,
    const float* __restrict__ rc_e, const float* __restrict__ rc_o,
    const float* __restrict__ T0_w, const float* __restrict__ T0_b,
    const float* __restrict__ UdFR, const float* __restrict__ UdFI,
    const float* __restrict__ UsFR, const float* __restrict__ UsFI,
    __nv_bfloat16* __restrict__ Ax)
{
    extern __shared__ float sm[];
    float* bufB = sm;
    float* bufC = sm + 16384;
    u64* rcoef = (u64*)(sm + 24576);
    u64* tws = (u64*)(sm + 24832);

    __shared__ float cv[16];

    int tid = threadIdx.x;
    int cg = blockIdx.x, b = blockIdx.y;
    int t_lane = tid >> 3, k = tid & 7, lane = tid & 31;

    if (tid < 128) rcoef[tid] = pk(rc_e[tid], rc_o[tid]);
    if (tid < 16) cv[tid] = coarse[(b * 2 + (tid >> 3)) * 512 + cg * 8 + (tid & 7)];
    __syncthreads();
    if (tid < 16) {
        int tt = tid >> 3, kk = tid & 7;
        float s = T0_b[kk];
#pragma unroll
        for (int kp = 0; kp < 8; kp++) s += T0_w[kk * 8 + kp] * cv[tt * 8 + kp];
        bufB[tid] = s;
    }
    __syncthreads();

    float* in = bufB;
    float* out = bufC;
    for (int i = NLVL - 1; i >= 1; i--) {
        int Lc = 2048 >> i;
        int nf = (Lc >> 1) + 1;
        int l = nf < 16 ? nf : 16;
        int nyq = (l == nf);
        const u64* twp = twI + 16 * (4096 - (4096 >> i));
        size_t specBase = (((size_t)i * 4 + b) * 16) * 512 + cg * 8 + k;
        recon_level(in, out, rcoef, twp, tws, UdFR, UdFI, UsFR, UsFI,
                    specBase, l, nyq, 1.f / (float)Lc, Lc, t_lane, k, lane, tid, (__nv_bfloat16*)0);
        __syncthreads();
        float* tmp = in; in = out; out = tmp;
    }
    // level 0: write bf16 split operand directly (only t < 1536 -> rows < 3072)
    {
        __nv_bfloat16* aout = Ax + (size_t)(b * LSEQ) * 1536 + cg * 8 + k;
        size_t specBase = (((size_t)0 * 4 + b) * 16) * 512 + cg * 8 + k;
        recon_level(in, out, rcoef, twI, tws, UdFR, UdFI, UsFR, UsFI,
                    specBase, 16, 0, 1.f / 2048.f, 1536, t_lane, k, lane, tid, aout);
    }
}

// ---------------- host orchestration ----------------
extern "C" void kernel_launch(void* const* d_in, const int* in_sizes, int n_in,
                              void* d_out, int out_size)
{
    const float* x     = (const float*)d_in[0];
    const float* Lk0_w = (const float*)d_in[1];
    const float* Lk0_b = (const float*)d_in[2];
    const float* Lk1_w = (const float*)d_in[3];
    const float* Lk1_b = (const float*)d_in[4];
    const float* T0_w  = (const float*)d_in[5];
    const float* T0_b  = (const float*)d_in[6];
    const float* Ar    = (const float*)d_in[7];
    const float* Ai    = (const float*)d_in[8];
    const float* Br    = (const float*)d_in[9];
    const float* Bi    = (const float*)d_in[10];
    const float* Cr    = (const float*)d_in[11];
    const float* Ci    = (const float*)d_in[12];
    const float* ec_s  = (const float*)d_in[13];
    const float* ec_d  = (const float*)d_in[14];
    const float* rc_e  = (const float*)d_in[15];
    const float* rc_o  = (const float*)d_in[16];

    float *vT, *coarse, *DfR, *DfI, *SfR, *SfI, *UdFR, *UdFI, *UsFR, *UsFI, *Wt;
    u64 *twF, *twI;
    __nv_bfloat16 *Ax, *Wx0, *Wx1;
    cudaGetSymbolAddress((void**)&vT, g_vT);
    cudaGetSymbolAddress((void**)&coarse, g_coarse);
    cudaGetSymbolAddress((void**)&DfR, g_DfR);
    cudaGetSymbolAddress((void**)&DfI, g_DfI);
    cudaGetSymbolAddress((void**)&SfR, g_SfR);
    cudaGetSymbolAddress((void**)&SfI, g_SfI);
    cudaGetSymbolAddress((void**)&UdFR, g_UdFR);
    cudaGetSymbolAddress((void**)&UdFI, g_UdFI);
    cudaGetSymbolAddress((void**)&UsFR, g_UsFR);
    cudaGetSymbolAddress((void**)&UsFI, g_UsFI);
    cudaGetSymbolAddress((void**)&Wt, g_Wt);
    cudaGetSymbolAddress((void**)&twF, g_twF);
    cudaGetSymbolAddress((void**)&twI, g_twI);
    cudaGetSymbolAddress((void**)&Ax, g_Ax);
    cudaGetSymbolAddress((void**)&Wx0, g_Wx0);
    cudaGetSymbolAddress((void**)&Wx1, g_Wx1);

    const int DECOMP_SMEM = 111104;
    const int RECON_SMEM  = 103936;
    cudaFuncSetAttribute(decomp_kernel, cudaFuncAttributeMaxDynamicSharedMemorySize, DECOMP_SMEM);
    cudaFuncSetAttribute(recon_fused, cudaFuncAttributeMaxDynamicSharedMemorySize, RECON_SMEM);

    twiddle_kernel<<<dim3(128, NLVL), 256>>>(twF, twI);
    transpose_w<<<dim3(4096, 6), 256>>>(Ar, Ai, Br, Bi, Cr, Ci, Wt);
    split_w_kernel<<<dim3(128, 2), 256>>>(Lk0_w, Lk1_w, Wx0, Wx1);
    split_x_kernel<<<4096, 256>>>(x, Ax);

    // Lk0 via warp-MMA tensor cores -> vT
    mma_gemm<<<dim3(4, 128), 256>>>(Ax, Wx0, Lk0_b, vT, 0);

    decomp_kernel<<<dim3(64, NB), 256, DECOMP_SMEM>>>(vT, twF, ec_s, ec_d,
                                                      DfR, DfI, SfR, SfI, coarse);

    // mix: register-prefetch pipelined, split accumulator chains
    mix_kernel<<<dim3(16, 16), 256>>>(Wt, DfR, DfI, SfR, SfI, UdFR, UdFI, UsFR, UsFI);

    // fused recon writes the bf16 split GEMM operand directly into Ax
    recon_fused<<<dim3(64, NB), 256, RECON_SMEM>>>(coarse, twI, rc_e, rc_o, T0_w, T0_b,
                                                   UdFR, UdFI, UsFR, UsFI, Ax);

    // Lk1 via warp-MMA tensor cores -> d_out
    mma_gemm<<<dim3(4, 96), 256>>>(Ax, Wx1, Lk1_b, (float*)d_out, 1);
}